// round 1
// baseline (speedup 1.0000x reference)
#include <cuda_runtime.h>
#include <math.h>

#define N_NODES 100000
#define N_EDGES 500000
// D_IN = 128, HID = 128, OUT = 64

// ---------------- scratch (static device globals; no allocation) ----------------
__device__ float g_h[N_NODES * 128];     // post-GEMM features (HID) / reused as relu output
__device__ float g_agg[N_NODES * 128];   // aggregation accumulator (HID)
__device__ float g_h3[N_NODES * 64];     // post-GEMM features (OUT)
__device__ float g_agg3[N_NODES * 64];   // aggregation accumulator (OUT)
__device__ float g_deg[N_NODES];
__device__ float g_dis[N_NODES];         // deg^{-1/2}
__device__ float g_invdeg[N_NODES];      // deg^{-1}

// ---------------- degree kernels ----------------
__global__ void deg_init_kernel() {
    int i = blockIdx.x * blockDim.x + threadIdx.x;
    if (i < N_NODES) g_deg[i] = 1.0f;   // self loop
}

__global__ void deg_count_kernel(const int* __restrict__ dst) {
    int e = blockIdx.x * blockDim.x + threadIdx.x;
    if (e < N_EDGES) atomicAdd(&g_deg[dst[e]], 1.0f);
}

__global__ void deg_finish_kernel() {
    int i = blockIdx.x * blockDim.x + threadIdx.x;
    if (i < N_NODES) {
        float d = g_deg[i];
        g_dis[i] = rsqrtf(d);
        g_invdeg[i] = 1.0f / d;
    }
}

// ---------------- SGEMM: C[M,BN] = A[M,128] @ B[128,BN] ----------------
// BM=128, BK=16, 256 threads, TM=8, TN = BN/16.
template <int BN, int TN>
__global__ void gemm_k128_kernel(const float* __restrict__ A,
                                 const float* __restrict__ B,
                                 float* __restrict__ C, int M) {
    constexpr int BM = 128;
    constexpr int BK = 16;
    constexpr int TM = 8;
    __shared__ float As[BK][BM];      // transposed A tile
    __shared__ float Bs[BK][BN];

    const int tid = threadIdx.x;                 // 0..255
    const int tx = tid % (BN / TN);              // 16 column groups
    const int ty = tid / (BN / TN);              // 16 row groups
    const int m0 = blockIdx.x * BM;

    float acc[TM][TN];
#pragma unroll
    for (int i = 0; i < TM; i++)
#pragma unroll
        for (int j = 0; j < TN; j++) acc[i][j] = 0.0f;

    for (int k0 = 0; k0 < 128; k0 += BK) {
        // load A tile: BM x BK = 512 float4
#pragma unroll
        for (int it = 0; it < 2; it++) {
            int f4 = tid + it * 256;          // 0..511
            int row = f4 >> 2;                // 4 float4 per row (16 floats)
            int c4 = f4 & 3;
            float4 v = make_float4(0.f, 0.f, 0.f, 0.f);
            int gr = m0 + row;
            if (gr < M) v = *(const float4*)&A[gr * 128 + k0 + c4 * 4];
            As[c4 * 4 + 0][row] = v.x;
            As[c4 * 4 + 1][row] = v.y;
            As[c4 * 4 + 2][row] = v.z;
            As[c4 * 4 + 3][row] = v.w;
        }
        // load B tile: BK x BN
        constexpr int BF4 = BK * BN / 4;
#pragma unroll
        for (int it = 0; it < BF4 / 256; it++) {
            int f4 = tid + it * 256;
            int row = f4 / (BN / 4);
            int c4 = f4 % (BN / 4);
            *(float4*)&Bs[row][c4 * 4] = *(const float4*)&B[(k0 + row) * BN + c4 * 4];
        }
        __syncthreads();
#pragma unroll
        for (int kk = 0; kk < BK; kk++) {
            float a[TM], b[TN];
#pragma unroll
            for (int i = 0; i < TM; i++) a[i] = As[kk][ty * TM + i];
#pragma unroll
            for (int j = 0; j < TN; j++) b[j] = Bs[kk][tx * TN + j];
#pragma unroll
            for (int i = 0; i < TM; i++)
#pragma unroll
                for (int j = 0; j < TN; j++) acc[i][j] = fmaf(a[i], b[j], acc[i][j]);
        }
        __syncthreads();
    }
#pragma unroll
    for (int i = 0; i < TM; i++) {
        int gr = m0 + ty * TM + i;
        if (gr < M) {
#pragma unroll
            for (int j = 0; j < TN; j += 4) {
                float4 v = make_float4(acc[i][j], acc[i][j + 1], acc[i][j + 2], acc[i][j + 3]);
                *(float4*)&C[gr * BN + tx * TN + j] = v;
            }
        }
    }
}

// ---------------- agg init: agg = h * invdeg[row] ----------------
template <int C>
__global__ void init_agg_kernel(const float* __restrict__ h, float* __restrict__ agg) {
    int idx = blockIdx.x * blockDim.x + threadIdx.x;   // float4 index
    if (idx < N_NODES * (C / 4)) {
        int row = idx / (C / 4);
        float s = g_invdeg[row];
        float4 v = ((const float4*)h)[idx];
        v.x *= s; v.y *= s; v.z *= s; v.w *= s;
        ((float4*)agg)[idx] = v;
    }
}

// ---------------- edge scatter: agg[dst] += h[src] * dis[src]*dis[dst] ----------------
template <int C>
__global__ void scatter_add_kernel(const int* __restrict__ src, const int* __restrict__ dst,
                                   const float* __restrict__ h, float* __restrict__ agg) {
    constexpr int LPE = C / 4;   // lanes per edge (32 for C=128, 16 for C=64)
    int gtid = blockIdx.x * blockDim.x + threadIdx.x;
    int e = gtid / LPE;
    int l = gtid % LPE;
    if (e >= N_EDGES) return;
    int s = src[e];
    int d = dst[e];
    float norm = g_dis[s] * g_dis[d];
    float4 v = *(const float4*)&h[s * C + l * 4];
    v.x *= norm; v.y *= norm; v.z *= norm; v.w *= norm;
    float* p = &agg[d * C + l * 4];
    asm volatile("red.global.add.v4.f32 [%0], {%1,%2,%3,%4};"
                 :: "l"(p), "f"(v.x), "f"(v.y), "f"(v.z), "f"(v.w)
                 : "memory");
}

// ---------------- bias (+ optional relu): out = act(agg + b) ----------------
template <int C, bool RELU>
__global__ void bias_act_kernel(const float* __restrict__ agg, const float* __restrict__ b,
                                float* __restrict__ out) {
    int idx = blockIdx.x * blockDim.x + threadIdx.x;   // float4 index
    if (idx < N_NODES * (C / 4)) {
        int c4 = idx % (C / 4);
        float4 bb = ((const float4*)b)[c4];
        float4 v = ((const float4*)agg)[idx];
        v.x += bb.x; v.y += bb.y; v.z += bb.z; v.w += bb.w;
        if (RELU) {
            v.x = fmaxf(v.x, 0.f); v.y = fmaxf(v.y, 0.f);
            v.z = fmaxf(v.z, 0.f); v.w = fmaxf(v.w, 0.f);
        }
        ((float4*)out)[idx] = v;
    }
}

// ---------------- decoder: sigmoid(dot(z[src], z[dst])) over 64 dims ----------------
__global__ void decoder_kernel(const float* __restrict__ z, const int* __restrict__ src,
                               const int* __restrict__ dst, float* __restrict__ out) {
    int gtid = blockIdx.x * blockDim.x + threadIdx.x;
    int e = gtid / 16;
    int l = gtid % 16;
    if (e >= N_EDGES) return;
    int s = src[e];
    int d = dst[e];
    float4 a = *(const float4*)&z[s * 64 + l * 4];
    float4 b = *(const float4*)&z[d * 64 + l * 4];
    float v = a.x * b.x + a.y * b.y + a.z * b.z + a.w * b.w;
    v += __shfl_xor_sync(0xffffffffu, v, 8);
    v += __shfl_xor_sync(0xffffffffu, v, 4);
    v += __shfl_xor_sync(0xffffffffu, v, 2);
    v += __shfl_xor_sync(0xffffffffu, v, 1);
    if (l == 0) out[e] = 1.0f / (1.0f + expf(-v));
}

// ---------------- launch ----------------
extern "C" void kernel_launch(void* const* d_in, const int* in_sizes, int n_in,
                              void* d_out, int out_size) {
    const float* xs = (const float*)d_in[0];
    const float* xt = (const float*)d_in[1];
    const int* s_ei = (const int*)d_in[2];
    const int* t_ei = (const int*)d_in[3];
    const float* W1 = (const float*)d_in[4];
    const float* b1 = (const float*)d_in[5];
    const float* W2 = (const float*)d_in[6];
    const float* b2 = (const float*)d_in[7];
    const float* W3 = (const float*)d_in[8];
    const float* b3 = (const float*)d_in[9];

    float* out = (float*)d_out;
    float* zs = out;
    float* zt = out + (size_t)N_NODES * 64;
    float* ps = out + (size_t)2 * N_NODES * 64;
    float* pt = ps + N_EDGES;

    float *h, *agg, *h3, *agg3;
    cudaGetSymbolAddress((void**)&h, g_h);
    cudaGetSymbolAddress((void**)&agg, g_agg);
    cudaGetSymbolAddress((void**)&h3, g_h3);
    cudaGetSymbolAddress((void**)&agg3, g_agg3);

    const int NB_NODE = (N_NODES + 255) / 256;
    const int NB_EDGE = (N_EDGES + 255) / 256;
    const int NB_GEMM = (N_NODES + 127) / 128;        // 782
    const int NB_EW128 = (N_NODES * 32) / 256;        // float4 elementwise, C=128 -> 12500
    const int NB_EW64 = (N_NODES * 16) / 256;         // C=64 -> 6250
    const int NB_SC128 = (N_EDGES * 32) / 256;        // 62500
    const int NB_SC64 = (N_EDGES * 16) / 256;         // 31250
    const int NB_DEC = (N_EDGES * 16) / 256;          // 31250

    for (int net = 0; net < 2; net++) {
        const float* x = net ? xt : xs;
        const float* Wa = net ? W2 : W1;
        const float* ba = net ? b2 : b1;
        const int* src = net ? t_ei : s_ei;
        const int* dst = src + N_EDGES;
        float* zout = net ? zt : zs;

        deg_init_kernel<<<NB_NODE, 256>>>();
        deg_count_kernel<<<NB_EDGE, 256>>>(dst);
        deg_finish_kernel<<<NB_NODE, 256>>>();

        // layer 1: conv(x, Wa, ba) -> relu -> h
        gemm_k128_kernel<128, 8><<<NB_GEMM, 256>>>(x, Wa, h, N_NODES);
        init_agg_kernel<128><<<NB_EW128, 256>>>(h, agg);
        scatter_add_kernel<128><<<NB_SC128, 256>>>(src, dst, h, agg);
        bias_act_kernel<128, true><<<NB_EW128, 256>>>(agg, ba, h);

        // layer 2 (shared W3): conv(h, W3, b3) -> z
        gemm_k128_kernel<64, 4><<<NB_GEMM, 256>>>(h, W3, h3, N_NODES);
        init_agg_kernel<64><<<NB_EW64, 256>>>(h3, agg3);
        scatter_add_kernel<64><<<NB_SC64, 256>>>(src, dst, h3, agg3);
        bias_act_kernel<64, false><<<NB_EW64, 256>>>(agg3, b3, zout);
    }

    decoder_kernel<<<NB_DEC, 256>>>(zs, s_ei, s_ei + N_EDGES, ps);
    decoder_kernel<<<NB_DEC, 256>>>(zt, t_ei, t_ei + N_EDGES, pt);
}

// round 3
// speedup vs baseline: 1.2145x; 1.2145x over previous
#include <cuda_runtime.h>
#include <cuda_bf16.h>
#include <math.h>
#include <stdint.h>

#define N_NODES 100000
#define N_EDGES 500000

// ---------------- scratch (static device globals; no allocation) ----------------
__device__ float g_h[N_NODES * 128];
__device__ float g_agg[N_NODES * 128];
__device__ float g_h3[N_NODES * 64];
__device__ float g_agg3[N_NODES * 64];
__device__ float g_deg[N_NODES];
__device__ float g_dis[N_NODES];
__device__ float g_invdeg[N_NODES];
__device__ __nv_bfloat16 g_abh[N_NODES * 128];   // layer2 A bf16 hi
__device__ __nv_bfloat16 g_abl[N_NODES * 128];   // layer2 A bf16 lo
// transposed weights [n][k] row-major, bf16 hi/lo
__device__ __nv_bfloat16 g_w1h[128 * 128], g_w1l[128 * 128];
__device__ __nv_bfloat16 g_w2h[128 * 128], g_w2l[128 * 128];
__device__ __nv_bfloat16 g_w3h[64 * 128],  g_w3l[64 * 128];

__device__ __forceinline__ uint32_t smem_u32(const void* p) {
    uint32_t a;
    asm("{ .reg .u64 t; cvta.to.shared.u64 t, %1; cvt.u32.u64 %0, t; }" : "=r"(a) : "l"(p));
    return a;
}

__device__ __forceinline__ void split_bf16(float v, __nv_bfloat16& hi, __nv_bfloat16& lo) {
    hi = __float2bfloat16_rn(v);
    lo = __float2bfloat16_rn(v - __bfloat162float(hi));
}

// ---------------- degree kernels ----------------
__global__ void deg_init_kernel() {
    int i = blockIdx.x * blockDim.x + threadIdx.x;
    if (i < N_NODES) g_deg[i] = 1.0f;
}
__global__ void deg_count_kernel(const int* __restrict__ dst) {
    int e = blockIdx.x * blockDim.x + threadIdx.x;
    if (e < N_EDGES) atomicAdd(&g_deg[dst[e]], 1.0f);
}
__global__ void deg_finish_kernel() {
    int i = blockIdx.x * blockDim.x + threadIdx.x;
    if (i < N_NODES) {
        float d = g_deg[i];
        g_dis[i] = rsqrtf(d);
        g_invdeg[i] = 1.0f / d;
    }
}

// ---------------- weight prep: transpose + bf16 split ----------------
__global__ void prep_weights_kernel(const float* __restrict__ W1, const float* __restrict__ W2,
                                    const float* __restrict__ W3) {
    int tid = blockIdx.x * blockDim.x + threadIdx.x;
    if (tid < 128 * 128) {
        int n = tid >> 7, k = tid & 127;
        __nv_bfloat16 hi, lo;
        split_bf16(W1[k * 128 + n], hi, lo);
        g_w1h[n * 128 + k] = hi; g_w1l[n * 128 + k] = lo;
        split_bf16(W2[k * 128 + n], hi, lo);
        g_w2h[n * 128 + k] = hi; g_w2l[n * 128 + k] = lo;
        if (n < 64) {
            split_bf16(W3[k * 64 + n], hi, lo);
            g_w3h[n * 128 + k] = hi; g_w3l[n * 128 + k] = lo;
        }
    }
}

// ---------------- bf16-split HMMA GEMM ----------------
// C[M,BN] = A[M,128] @ B^T (B stored [BN][128] row-major, hi/lo split)
// epilogue: Ch = C ; Cagg = C * invdeg[row]
// BM=128, BK=32, 256 threads (8 warps as 4m x 2n), warp tile 32 x BN/2.
// 3 accumulating passes: Ah*Bh + Ah*Bl + Al*Bh.
#define SKP 40   // padded smem stride (conflict-free ldmatrix: 80B row stride)

template <int BN, bool AF32>
__global__ void __launch_bounds__(256) gemm_mma_kernel(
        const float* __restrict__ Af,
        const __nv_bfloat16* __restrict__ Ah_g, const __nv_bfloat16* __restrict__ Al_g,
        const __nv_bfloat16* __restrict__ Bh_g, const __nv_bfloat16* __restrict__ Bl_g,
        float* __restrict__ Ch, float* __restrict__ Cagg, int M) {
    constexpr int NT = BN / 16;          // n-tiles per warp (8 or 4)
    __shared__ __nv_bfloat16 sAh[128][SKP];
    __shared__ __nv_bfloat16 sAl[128][SKP];
    __shared__ __nv_bfloat16 sBh[BN][SKP];
    __shared__ __nv_bfloat16 sBl[BN][SKP];

    const int tid = threadIdx.x;
    const int wid = tid >> 5, lane = tid & 31;
    const int warp_m = (wid & 3) * 32;
    const int warp_n = (wid >> 2) * (BN / 2);
    const int m0 = blockIdx.x * 128;

    float acc[2][NT][4];
#pragma unroll
    for (int mt = 0; mt < 2; mt++)
#pragma unroll
        for (int nt = 0; nt < NT; nt++)
#pragma unroll
            for (int r = 0; r < 4; r++) acc[mt][nt][r] = 0.0f;

    const uint32_t sAh_b = smem_u32(&sAh[0][0]);
    const uint32_t sAl_b = smem_u32(&sAl[0][0]);
    const uint32_t sBh_b = smem_u32(&sBh[0][0]);
    const uint32_t sBl_b = smem_u32(&sBl[0][0]);

    // per-lane ldmatrix source coordinates
    const int a_row = warp_m + (lane & 15);          // + mt*16
    const int a_khalf = (lane >> 4) << 3;            // + ks*16
    const int b_row = warp_n + (lane & 7);           // + nt*8
    const int b_khalf = lane & 8;                    // + ks*16

    for (int k0 = 0; k0 < 128; k0 += 32) {
        // ---- load A chunk ----
        if (AF32) {
            // 128 rows x 32 fp32 = 1024 float4; split to bf16 hi/lo
#pragma unroll
            for (int it = 0; it < 4; it++) {
                int i = tid + it * 256;
                int r = i >> 3, c = (i & 7) * 4;
                float4 v = make_float4(0.f, 0.f, 0.f, 0.f);
                if (m0 + r < M) v = *(const float4*)&Af[(size_t)(m0 + r) * 128 + k0 + c];
                __nv_bfloat16 h0, h1, h2, h3, l0, l1, l2, l3;
                split_bf16(v.x, h0, l0); split_bf16(v.y, h1, l1);
                split_bf16(v.z, h2, l2); split_bf16(v.w, h3, l3);
                __nv_bfloat162 ph0 = {h0, h1}, ph1 = {h2, h3};
                __nv_bfloat162 pl0 = {l0, l1}, pl1 = {l2, l3};
                *(uint2*)&sAh[r][c] = make_uint2(*(uint32_t*)&ph0, *(uint32_t*)&ph1);
                *(uint2*)&sAl[r][c] = make_uint2(*(uint32_t*)&pl0, *(uint32_t*)&pl1);
            }
        } else {
            // 128 rows x 32 bf16 = 512 uint4 per array
#pragma unroll
            for (int it = 0; it < 2; it++) {
                int i = tid + it * 256;
                int r = i >> 2, q = i & 3;
                uint4 vh = make_uint4(0, 0, 0, 0), vl = make_uint4(0, 0, 0, 0);
                if (m0 + r < M) {
                    vh = *(const uint4*)&Ah_g[(size_t)(m0 + r) * 128 + k0 + q * 8];
                    vl = *(const uint4*)&Al_g[(size_t)(m0 + r) * 128 + k0 + q * 8];
                }
                *(uint4*)&sAh[r][q * 8] = vh;
                *(uint4*)&sAl[r][q * 8] = vl;
            }
        }
        // ---- load B chunk: BN rows x 32 bf16 ----
        {
            constexpr int NV = BN * 4;   // uint4 count per array
#pragma unroll
            for (int it = 0; it < NV / 256; it++) {
                int i = tid + it * 256;
                int r = i >> 2, q = i & 3;
                *(uint4*)&sBh[r][q * 8] = *(const uint4*)&Bh_g[r * 128 + k0 + q * 8];
                *(uint4*)&sBl[r][q * 8] = *(const uint4*)&Bl_g[r * 128 + k0 + q * 8];
            }
            if (BN == 64 && tid < 256) {   // BN==64: 256 uint4, handled in it==0 above
            }
        }
        __syncthreads();

        // ---- compute: 3 split passes x 2 k16 steps ----
#pragma unroll
        for (int pass = 0; pass < 3; pass++) {
            const uint32_t aBase = (pass < 2) ? sAh_b : sAl_b;
            const uint32_t bBase = (pass == 1) ? sBl_b : sBh_b;
#pragma unroll
            for (int ks = 0; ks < 2; ks++) {
                uint32_t af[2][4];
#pragma unroll
                for (int mt = 0; mt < 2; mt++) {
                    uint32_t addr = aBase +
                        ((a_row + mt * 16) * SKP + ks * 16 + a_khalf) * 2;
                    asm volatile(
                        "ldmatrix.sync.aligned.m8n8.x4.shared.b16 {%0,%1,%2,%3}, [%4];"
                        : "=r"(af[mt][0]), "=r"(af[mt][1]), "=r"(af[mt][2]), "=r"(af[mt][3])
                        : "r"(addr));
                }
#pragma unroll
                for (int nt = 0; nt < NT; nt++) {
                    uint32_t b0, b1;
                    uint32_t addr = bBase +
                        ((b_row + nt * 8) * SKP + ks * 16 + b_khalf) * 2;
                    asm volatile(
                        "ldmatrix.sync.aligned.m8n8.x2.shared.b16 {%0,%1}, [%2];"
                        : "=r"(b0), "=r"(b1) : "r"(addr));
#pragma unroll
                    for (int mt = 0; mt < 2; mt++) {
                        asm volatile(
                            "mma.sync.aligned.m16n8k16.row.col.f32.bf16.bf16.f32 "
                            "{%0,%1,%2,%3}, {%4,%5,%6,%7}, {%8,%9}, {%0,%1,%2,%3};"
                            : "+f"(acc[mt][nt][0]), "+f"(acc[mt][nt][1]),
                              "+f"(acc[mt][nt][2]), "+f"(acc[mt][nt][3])
                            : "r"(af[mt][0]), "r"(af[mt][1]), "r"(af[mt][2]), "r"(af[mt][3]),
                              "r"(b0), "r"(b1));
                    }
                }
            }
        }
        __syncthreads();
    }

    // ---- epilogue: Ch = C, Cagg = C * invdeg[row] ----
#pragma unroll
    for (int mt = 0; mt < 2; mt++) {
        int r0 = m0 + warp_m + mt * 16 + (lane >> 2);
        int r1 = r0 + 8;
        float inv0 = (r0 < M) ? g_invdeg[r0] : 0.f;
        float inv1 = (r1 < M) ? g_invdeg[r1] : 0.f;
#pragma unroll
        for (int nt = 0; nt < NT; nt++) {
            int n0 = warp_n + nt * 8 + 2 * (lane & 3);
            if (r0 < M) {
                *(float2*)&Ch[(size_t)r0 * BN + n0] = make_float2(acc[mt][nt][0], acc[mt][nt][1]);
                *(float2*)&Cagg[(size_t)r0 * BN + n0] =
                    make_float2(acc[mt][nt][0] * inv0, acc[mt][nt][1] * inv0);
            }
            if (r1 < M) {
                *(float2*)&Ch[(size_t)r1 * BN + n0] = make_float2(acc[mt][nt][2], acc[mt][nt][3]);
                *(float2*)&Cagg[(size_t)r1 * BN + n0] =
                    make_float2(acc[mt][nt][2] * inv1, acc[mt][nt][3] * inv1);
            }
        }
    }
}

// ---------------- edge scatter: agg[dst] += h[src] * dis[src]*dis[dst] ----------------
template <int C>
__global__ void scatter_add_kernel(const int* __restrict__ src, const int* __restrict__ dst,
                                   const float* __restrict__ h, float* __restrict__ agg) {
    constexpr int LPE = C / 4;
    int gtid = blockIdx.x * blockDim.x + threadIdx.x;
    int e = gtid / LPE;
    int l = gtid % LPE;
    if (e >= N_EDGES) return;
    int s = src[e];
    int d = dst[e];
    float norm = g_dis[s] * g_dis[d];
    float4 v = *(const float4*)&h[(size_t)s * C + l * 4];
    v.x *= norm; v.y *= norm; v.z *= norm; v.w *= norm;
    float* p = &agg[(size_t)d * C + l * 4];
    asm volatile("red.global.add.v4.f32 [%0], {%1,%2,%3,%4};"
                 :: "l"(p), "f"(v.x), "f"(v.y), "f"(v.z), "f"(v.w) : "memory");
}

// ---------------- bias+relu -> bf16 hi/lo split (feeds layer-2 GEMM A) ----------------
__global__ void bias_relu_bf16_kernel(const float* __restrict__ agg, const float* __restrict__ b) {
    int idx = blockIdx.x * blockDim.x + threadIdx.x;
    if (idx < N_NODES * 32) {
        int c4 = idx & 31;
        float4 bb = ((const float4*)b)[c4];
        float4 v = ((const float4*)agg)[idx];
        v.x = fmaxf(v.x + bb.x, 0.f); v.y = fmaxf(v.y + bb.y, 0.f);
        v.z = fmaxf(v.z + bb.z, 0.f); v.w = fmaxf(v.w + bb.w, 0.f);
        __nv_bfloat16 h0, h1, h2, h3, l0, l1, l2, l3;
        split_bf16(v.x, h0, l0); split_bf16(v.y, h1, l1);
        split_bf16(v.z, h2, l2); split_bf16(v.w, h3, l3);
        __nv_bfloat162 ph0 = {h0, h1}, ph1 = {h2, h3}, pl0 = {l0, l1}, pl1 = {l2, l3};
        ((uint2*)g_abh)[idx] = make_uint2(*(uint32_t*)&ph0, *(uint32_t*)&ph1);
        ((uint2*)g_abl)[idx] = make_uint2(*(uint32_t*)&pl0, *(uint32_t*)&pl1);
    }
}

// ---------------- final bias: zout = agg3 + b3 ----------------
__global__ void bias64_kernel(const float* __restrict__ agg, const float* __restrict__ b,
                              float* __restrict__ out) {
    int idx = blockIdx.x * blockDim.x + threadIdx.x;
    if (idx < N_NODES * 16) {
        int c4 = idx & 15;
        float4 bb = ((const float4*)b)[c4];
        float4 v = ((const float4*)agg)[idx];
        v.x += bb.x; v.y += bb.y; v.z += bb.z; v.w += bb.w;
        ((float4*)out)[idx] = v;
    }
}

// ---------------- decoder ----------------
__global__ void decoder_kernel(const float* __restrict__ z, const int* __restrict__ src,
                               const int* __restrict__ dst, float* __restrict__ out) {
    int gtid = blockIdx.x * blockDim.x + threadIdx.x;
    int e = gtid / 16;
    int l = gtid % 16;
    if (e >= N_EDGES) return;
    int s = src[e];
    int d = dst[e];
    float4 a = *(const float4*)&z[(size_t)s * 64 + l * 4];
    float4 b = *(const float4*)&z[(size_t)d * 64 + l * 4];
    float v = a.x * b.x + a.y * b.y + a.z * b.z + a.w * b.w;
    v += __shfl_xor_sync(0xffffffffu, v, 8);
    v += __shfl_xor_sync(0xffffffffu, v, 4);
    v += __shfl_xor_sync(0xffffffffu, v, 2);
    v += __shfl_xor_sync(0xffffffffu, v, 1);
    if (l == 0) out[e] = 1.0f / (1.0f + expf(-v));
}

// ---------------- launch ----------------
extern "C" void kernel_launch(void* const* d_in, const int* in_sizes, int n_in,
                              void* d_out, int out_size) {
    const float* xs = (const float*)d_in[0];
    const float* xt = (const float*)d_in[1];
    const int* s_ei = (const int*)d_in[2];
    const int* t_ei = (const int*)d_in[3];
    const float* W1 = (const float*)d_in[4];
    const float* b1 = (const float*)d_in[5];
    const float* W2 = (const float*)d_in[6];
    const float* b2 = (const float*)d_in[7];
    const float* W3 = (const float*)d_in[8];
    const float* b3 = (const float*)d_in[9];

    float* out = (float*)d_out;
    float* zs = out;
    float* zt = out + (size_t)N_NODES * 64;
    float* ps = out + (size_t)2 * N_NODES * 64;
    float* pt = ps + N_EDGES;

    float *h, *agg, *h3, *agg3;
    cudaGetSymbolAddress((void**)&h, g_h);
    cudaGetSymbolAddress((void**)&agg, g_agg);
    cudaGetSymbolAddress((void**)&h3, g_h3);
    cudaGetSymbolAddress((void**)&agg3, g_agg3);
    __nv_bfloat16 *abh, *abl, *w1h, *w1l, *w2h, *w2l, *w3h, *w3l;
    cudaGetSymbolAddress((void**)&abh, g_abh);
    cudaGetSymbolAddress((void**)&abl, g_abl);
    cudaGetSymbolAddress((void**)&w1h, g_w1h);
    cudaGetSymbolAddress((void**)&w1l, g_w1l);
    cudaGetSymbolAddress((void**)&w2h, g_w2h);
    cudaGetSymbolAddress((void**)&w2l, g_w2l);
    cudaGetSymbolAddress((void**)&w3h, g_w3h);
    cudaGetSymbolAddress((void**)&w3l, g_w3l);

    const int NB_NODE = (N_NODES + 255) / 256;
    const int NB_EDGE = (N_EDGES + 255) / 256;
    const int NB_GEMM = (N_NODES + 127) / 128;     // 782
    const int NB_EW128 = (N_NODES * 32) / 256;
    const int NB_EW64 = (N_NODES * 16) / 256;
    const int NB_SC128 = (N_EDGES * 32) / 256;
    const int NB_SC64 = (N_EDGES * 16) / 256;
    const int NB_DEC = (N_EDGES * 16) / 256;

    prep_weights_kernel<<<64, 256>>>(W1, W2, W3);

    for (int net = 0; net < 2; net++) {
        const float* x = net ? xt : xs;
        const __nv_bfloat16* wah = net ? w2h : w1h;
        const __nv_bfloat16* wal = net ? w2l : w1l;
        const float* ba = net ? b2 : b1;
        const int* src = net ? t_ei : s_ei;
        const int* dst = src + N_EDGES;
        float* zout = net ? zt : zs;

        deg_init_kernel<<<NB_NODE, 256>>>();
        deg_count_kernel<<<NB_EDGE, 256>>>(dst);
        deg_finish_kernel<<<NB_NODE, 256>>>();

        // layer 1: h = x@W (fused agg init); scatter; bias+relu -> bf16 split
        gemm_mma_kernel<128, true><<<NB_GEMM, 256>>>(x, nullptr, nullptr, wah, wal,
                                                     h, agg, N_NODES);
        scatter_add_kernel<128><<<NB_SC128, 256>>>(src, dst, h, agg);
        bias_relu_bf16_kernel<<<NB_EW128, 256>>>(agg, ba);

        // layer 2 (shared W3)
        gemm_mma_kernel<64, false><<<NB_GEMM, 256>>>(nullptr, abh, abl, w3h, w3l,
                                                     h3, agg3, N_NODES);
        scatter_add_kernel<64><<<NB_SC64, 256>>>(src, dst, h3, agg3);
        bias64_kernel<<<NB_EW64, 256>>>(agg3, b3, zout);
    }

    decoder_kernel<<<NB_DEC, 256>>>(zs, s_ei, s_ei + N_EDGES, ps);
    decoder_kernel<<<NB_DEC, 256>>>(zt, t_ei, t_ei + N_EDGES, pt);
}

// round 4
// speedup vs baseline: 1.6058x; 1.3222x over previous
#include <cuda_runtime.h>
#include <cuda_bf16.h>
#include <math.h>
#include <stdint.h>

#define N_NODES 100000
#define N_EDGES 500000

// ---------------- scratch (static device globals; no allocation) ----------------
__device__ float g_h[N_NODES * 128];
__device__ float g_h3[N_NODES * 64];
__device__ float g_dis[N_NODES];
__device__ float g_invdeg[N_NODES];
__device__ int g_cnt[N_NODES];
__device__ int g_rowstart[N_NODES + 1];
__device__ int g_cursor[N_NODES];
__device__ int g_blocksums[512];
__device__ int g_csr_src[N_EDGES];
__device__ float g_csr_norm[N_EDGES];
__device__ __nv_bfloat16 g_abh[N_NODES * 128];   // layer2 A bf16 hi
__device__ __nv_bfloat16 g_abl[N_NODES * 128];   // layer2 A bf16 lo
// transposed weights [n][k] row-major, bf16 hi/lo
__device__ __nv_bfloat16 g_w1h[128 * 128], g_w1l[128 * 128];
__device__ __nv_bfloat16 g_w2h[128 * 128], g_w2l[128 * 128];
__device__ __nv_bfloat16 g_w3h[64 * 128],  g_w3l[64 * 128];

__device__ __forceinline__ uint32_t smem_u32(const void* p) {
    uint32_t a;
    asm("{ .reg .u64 t; cvta.to.shared.u64 t, %1; cvt.u32.u64 %0, t; }" : "=r"(a) : "l"(p));
    return a;
}
__device__ __forceinline__ void split_bf16(float v, __nv_bfloat16& hi, __nv_bfloat16& lo) {
    hi = __float2bfloat16_rn(v);
    lo = __float2bfloat16_rn(v - __bfloat162float(hi));
}

// ---------------- degree + CSR build ----------------
__global__ void deg_init_kernel() {
    int i = blockIdx.x * blockDim.x + threadIdx.x;
    if (i < N_NODES) g_cnt[i] = 0;
}
__global__ void deg_count_kernel(const int* __restrict__ dst) {
    int e = blockIdx.x * blockDim.x + threadIdx.x;
    if (e < N_EDGES) atomicAdd(&g_cnt[dst[e]], 1);
}
__global__ void deg_finish_kernel() {
    int i = blockIdx.x * blockDim.x + threadIdx.x;
    if (i < N_NODES) {
        float d = (float)g_cnt[i] + 1.0f;
        g_dis[i] = rsqrtf(d);
        g_invdeg[i] = 1.0f / d;
    }
}
// block-level exclusive scan of counts (391 blocks x 256)
__global__ void scan1_kernel() {
    __shared__ int s[2][256];
    int tid = threadIdx.x;
    int i = blockIdx.x * 256 + tid;
    int v = (i < N_NODES) ? g_cnt[i] : 0;
    int buf = 0;
    s[0][tid] = v;
    __syncthreads();
#pragma unroll
    for (int off = 1; off < 256; off <<= 1) {
        int nb = buf ^ 1;
        s[nb][tid] = s[buf][tid] + (tid >= off ? s[buf][tid - off] : 0);
        buf = nb;
        __syncthreads();
    }
    if (i < N_NODES) g_rowstart[i] = s[buf][tid] - v;   // exclusive, block-local
    if (tid == 255) g_blocksums[blockIdx.x] = s[buf][255];
}
__global__ void scan2_kernel(int nblocks) {
    __shared__ int s[2][512];
    int tid = threadIdx.x;
    int v = (tid < nblocks) ? g_blocksums[tid] : 0;
    int buf = 0;
    s[0][tid] = v;
    __syncthreads();
#pragma unroll
    for (int off = 1; off < 512; off <<= 1) {
        int nb = buf ^ 1;
        s[nb][tid] = s[buf][tid] + (tid >= off ? s[buf][tid - off] : 0);
        buf = nb;
        __syncthreads();
    }
    g_blocksums[tid] = s[buf][tid] - v;   // exclusive block offsets
}
__global__ void scan3_kernel() {
    int i = blockIdx.x * blockDim.x + threadIdx.x;
    if (i < N_NODES) {
        g_rowstart[i] += g_blocksums[i >> 8];
        g_cursor[i] = 0;
    }
    if (i == 0) g_rowstart[N_NODES] = N_EDGES;
}
__global__ void csr_fill_kernel(const int* __restrict__ src, const int* __restrict__ dst) {
    int e = blockIdx.x * blockDim.x + threadIdx.x;
    if (e >= N_EDGES) return;
    int s = src[e], d = dst[e];
    int pos = g_rowstart[d] + atomicAdd(&g_cursor[d], 1);
    g_csr_src[pos] = s;
    g_csr_norm[pos] = g_dis[s] * g_dis[d];
}

// ---------------- weight prep: transpose + bf16 split ----------------
__global__ void prep_weights_kernel(const float* __restrict__ W1, const float* __restrict__ W2,
                                    const float* __restrict__ W3) {
    int tid = blockIdx.x * blockDim.x + threadIdx.x;
    if (tid < 128 * 128) {
        int n = tid >> 7, k = tid & 127;
        __nv_bfloat16 hi, lo;
        split_bf16(W1[k * 128 + n], hi, lo);
        g_w1h[n * 128 + k] = hi; g_w1l[n * 128 + k] = lo;
        split_bf16(W2[k * 128 + n], hi, lo);
        g_w2h[n * 128 + k] = hi; g_w2l[n * 128 + k] = lo;
        if (n < 64) {
            split_bf16(W3[k * 64 + n], hi, lo);
            g_w3h[n * 128 + k] = hi; g_w3l[n * 128 + k] = lo;
        }
    }
}

// ---------------- bf16-split HMMA GEMM: C[M,BN] = A[M,128] @ B^T ----------------
#define SKP 40

template <int BN, bool AF32>
__global__ void __launch_bounds__(256) gemm_mma_kernel(
        const float* __restrict__ Af,
        const __nv_bfloat16* __restrict__ Ah_g, const __nv_bfloat16* __restrict__ Al_g,
        const __nv_bfloat16* __restrict__ Bh_g, const __nv_bfloat16* __restrict__ Bl_g,
        float* __restrict__ Ch, int M) {
    constexpr int NT = BN / 16;
    __shared__ __nv_bfloat16 sAh[128][SKP];
    __shared__ __nv_bfloat16 sAl[128][SKP];
    __shared__ __nv_bfloat16 sBh[BN][SKP];
    __shared__ __nv_bfloat16 sBl[BN][SKP];

    const int tid = threadIdx.x;
    const int wid = tid >> 5, lane = tid & 31;
    const int warp_m = (wid & 3) * 32;
    const int warp_n = (wid >> 2) * (BN / 2);
    const int m0 = blockIdx.x * 128;

    float acc[2][NT][4];
#pragma unroll
    for (int mt = 0; mt < 2; mt++)
#pragma unroll
        for (int nt = 0; nt < NT; nt++)
#pragma unroll
            for (int r = 0; r < 4; r++) acc[mt][nt][r] = 0.0f;

    const uint32_t sAh_b = smem_u32(&sAh[0][0]);
    const uint32_t sAl_b = smem_u32(&sAl[0][0]);
    const uint32_t sBh_b = smem_u32(&sBh[0][0]);
    const uint32_t sBl_b = smem_u32(&sBl[0][0]);

    const int a_row = warp_m + (lane & 15);
    const int a_khalf = (lane >> 4) << 3;
    const int b_row = warp_n + (lane & 7);
    const int b_khalf = lane & 8;

    for (int k0 = 0; k0 < 128; k0 += 32) {
        if (AF32) {
#pragma unroll
            for (int it = 0; it < 4; it++) {
                int i = tid + it * 256;
                int r = i >> 3, c = (i & 7) * 4;
                float4 v = make_float4(0.f, 0.f, 0.f, 0.f);
                if (m0 + r < M) v = *(const float4*)&Af[(size_t)(m0 + r) * 128 + k0 + c];
                __nv_bfloat16 h0, h1, h2, h3, l0, l1, l2, l3;
                split_bf16(v.x, h0, l0); split_bf16(v.y, h1, l1);
                split_bf16(v.z, h2, l2); split_bf16(v.w, h3, l3);
                __nv_bfloat162 ph0 = {h0, h1}, ph1 = {h2, h3};
                __nv_bfloat162 pl0 = {l0, l1}, pl1 = {l2, l3};
                *(uint2*)&sAh[r][c] = make_uint2(*(uint32_t*)&ph0, *(uint32_t*)&ph1);
                *(uint2*)&sAl[r][c] = make_uint2(*(uint32_t*)&pl0, *(uint32_t*)&pl1);
            }
        } else {
#pragma unroll
            for (int it = 0; it < 2; it++) {
                int i = tid + it * 256;
                int r = i >> 2, q = i & 3;
                uint4 vh = make_uint4(0, 0, 0, 0), vl = make_uint4(0, 0, 0, 0);
                if (m0 + r < M) {
                    vh = *(const uint4*)&Ah_g[(size_t)(m0 + r) * 128 + k0 + q * 8];
                    vl = *(const uint4*)&Al_g[(size_t)(m0 + r) * 128 + k0 + q * 8];
                }
                *(uint4*)&sAh[r][q * 8] = vh;
                *(uint4*)&sAl[r][q * 8] = vl;
            }
        }
        {
            constexpr int NV = BN * 4;
#pragma unroll
            for (int it = 0; it < NV / 256; it++) {
                int i = tid + it * 256;
                int r = i >> 2, q = i & 3;
                *(uint4*)&sBh[r][q * 8] = *(const uint4*)&Bh_g[r * 128 + k0 + q * 8];
                *(uint4*)&sBl[r][q * 8] = *(const uint4*)&Bl_g[r * 128 + k0 + q * 8];
            }
        }
        __syncthreads();

#pragma unroll
        for (int pass = 0; pass < 3; pass++) {
            const uint32_t aBase = (pass < 2) ? sAh_b : sAl_b;
            const uint32_t bBase = (pass == 1) ? sBl_b : sBh_b;
#pragma unroll
            for (int ks = 0; ks < 2; ks++) {
                uint32_t af[2][4];
#pragma unroll
                for (int mt = 0; mt < 2; mt++) {
                    uint32_t addr = aBase + ((a_row + mt * 16) * SKP + ks * 16 + a_khalf) * 2;
                    asm volatile(
                        "ldmatrix.sync.aligned.m8n8.x4.shared.b16 {%0,%1,%2,%3}, [%4];"
                        : "=r"(af[mt][0]), "=r"(af[mt][1]), "=r"(af[mt][2]), "=r"(af[mt][3])
                        : "r"(addr));
                }
#pragma unroll
                for (int nt = 0; nt < NT; nt++) {
                    uint32_t b0, b1;
                    uint32_t addr = bBase + ((b_row + nt * 8) * SKP + ks * 16 + b_khalf) * 2;
                    asm volatile(
                        "ldmatrix.sync.aligned.m8n8.x2.shared.b16 {%0,%1}, [%2];"
                        : "=r"(b0), "=r"(b1) : "r"(addr));
#pragma unroll
                    for (int mt = 0; mt < 2; mt++) {
                        asm volatile(
                            "mma.sync.aligned.m16n8k16.row.col.f32.bf16.bf16.f32 "
                            "{%0,%1,%2,%3}, {%4,%5,%6,%7}, {%8,%9}, {%0,%1,%2,%3};"
                            : "+f"(acc[mt][nt][0]), "+f"(acc[mt][nt][1]),
                              "+f"(acc[mt][nt][2]), "+f"(acc[mt][nt][3])
                            : "r"(af[mt][0]), "r"(af[mt][1]), "r"(af[mt][2]), "r"(af[mt][3]),
                              "r"(b0), "r"(b1));
                    }
                }
            }
        }
        __syncthreads();
    }

#pragma unroll
    for (int mt = 0; mt < 2; mt++) {
        int r0 = m0 + warp_m + mt * 16 + (lane >> 2);
        int r1 = r0 + 8;
#pragma unroll
        for (int nt = 0; nt < NT; nt++) {
            int n0 = warp_n + nt * 8 + 2 * (lane & 3);
            if (r0 < M)
                *(float2*)&Ch[(size_t)r0 * BN + n0] = make_float2(acc[mt][nt][0], acc[mt][nt][1]);
            if (r1 < M)
                *(float2*)&Ch[(size_t)r1 * BN + n0] = make_float2(acc[mt][nt][2], acc[mt][nt][3]);
        }
    }
}

// ---------------- CSR aggregation, C=128: fused bias+relu+bf16 split ----------------
// warp per node; lane owns 4 columns
__global__ void __launch_bounds__(256) agg128_kernel(const float* __restrict__ h,
                                                     const float* __restrict__ b) {
    int node = blockIdx.x * 8 + (threadIdx.x >> 5);
    int lane = threadIdx.x & 31;
    if (node >= N_NODES) return;
    float inv = g_invdeg[node];
    float4 acc = *(const float4*)&h[(size_t)node * 128 + lane * 4];
    acc.x *= inv; acc.y *= inv; acc.z *= inv; acc.w *= inv;
    int beg = g_rowstart[node], end = g_rowstart[node + 1];
    for (int i = beg; i < end; i++) {
        int s = g_csr_src[i];
        float nrm = g_csr_norm[i];
        float4 v = *(const float4*)&h[(size_t)s * 128 + lane * 4];
        acc.x = fmaf(v.x, nrm, acc.x);
        acc.y = fmaf(v.y, nrm, acc.y);
        acc.z = fmaf(v.z, nrm, acc.z);
        acc.w = fmaf(v.w, nrm, acc.w);
    }
    float4 bb = ((const float4*)b)[lane];
    acc.x = fmaxf(acc.x + bb.x, 0.f); acc.y = fmaxf(acc.y + bb.y, 0.f);
    acc.z = fmaxf(acc.z + bb.z, 0.f); acc.w = fmaxf(acc.w + bb.w, 0.f);
    __nv_bfloat16 h0, h1, h2, h3, l0, l1, l2, l3;
    split_bf16(acc.x, h0, l0); split_bf16(acc.y, h1, l1);
    split_bf16(acc.z, h2, l2); split_bf16(acc.w, h3, l3);
    __nv_bfloat162 ph0 = {h0, h1}, ph1 = {h2, h3}, pl0 = {l0, l1}, pl1 = {l2, l3};
    int idx = node * 32 + lane;
    ((uint2*)g_abh)[idx] = make_uint2(*(uint32_t*)&ph0, *(uint32_t*)&ph1);
    ((uint2*)g_abl)[idx] = make_uint2(*(uint32_t*)&pl0, *(uint32_t*)&pl1);
}

// ---------------- CSR aggregation, C=64: fused +b3, fp32 out ----------------
// half-warp per node; lane owns 4 columns
__global__ void __launch_bounds__(256) agg64_kernel(const float* __restrict__ h3,
                                                    const float* __restrict__ b,
                                                    float* __restrict__ out) {
    int node = blockIdx.x * 16 + (threadIdx.x >> 4);
    int l = threadIdx.x & 15;
    if (node >= N_NODES) return;
    float inv = g_invdeg[node];
    float4 acc = *(const float4*)&h3[(size_t)node * 64 + l * 4];
    acc.x *= inv; acc.y *= inv; acc.z *= inv; acc.w *= inv;
    int beg = g_rowstart[node], end = g_rowstart[node + 1];
    for (int i = beg; i < end; i++) {
        int s = g_csr_src[i];
        float nrm = g_csr_norm[i];
        float4 v = *(const float4*)&h3[(size_t)s * 64 + l * 4];
        acc.x = fmaf(v.x, nrm, acc.x);
        acc.y = fmaf(v.y, nrm, acc.y);
        acc.z = fmaf(v.z, nrm, acc.z);
        acc.w = fmaf(v.w, nrm, acc.w);
    }
    float4 bb = ((const float4*)b)[l];
    acc.x += bb.x; acc.y += bb.y; acc.z += bb.z; acc.w += bb.w;
    *(float4*)&out[(size_t)node * 64 + l * 4] = acc;
}

// ---------------- decoder ----------------
__global__ void decoder_kernel(const float* __restrict__ z, const int* __restrict__ src,
                               const int* __restrict__ dst, float* __restrict__ out) {
    int gtid = blockIdx.x * blockDim.x + threadIdx.x;
    int e = gtid / 16;
    int l = gtid % 16;
    if (e >= N_EDGES) return;
    int s = src[e];
    int d = dst[e];
    float4 a = *(const float4*)&z[(size_t)s * 64 + l * 4];
    float4 b = *(const float4*)&z[(size_t)d * 64 + l * 4];
    float v = a.x * b.x + a.y * b.y + a.z * b.z + a.w * b.w;
    v += __shfl_xor_sync(0xffffffffu, v, 8);
    v += __shfl_xor_sync(0xffffffffu, v, 4);
    v += __shfl_xor_sync(0xffffffffu, v, 2);
    v += __shfl_xor_sync(0xffffffffu, v, 1);
    if (l == 0) out[e] = 1.0f / (1.0f + expf(-v));
}

// ---------------- launch ----------------
extern "C" void kernel_launch(void* const* d_in, const int* in_sizes, int n_in,
                              void* d_out, int out_size) {
    const float* xs = (const float*)d_in[0];
    const float* xt = (const float*)d_in[1];
    const int* s_ei = (const int*)d_in[2];
    const int* t_ei = (const int*)d_in[3];
    const float* W1 = (const float*)d_in[4];
    const float* b1 = (const float*)d_in[5];
    const float* W2 = (const float*)d_in[6];
    const float* b2 = (const float*)d_in[7];
    const float* W3 = (const float*)d_in[8];
    const float* b3 = (const float*)d_in[9];

    float* out = (float*)d_out;
    float* zs = out;
    float* zt = out + (size_t)N_NODES * 64;
    float* ps = out + (size_t)2 * N_NODES * 64;
    float* pt = ps + N_EDGES;

    float *h, *h3;
    cudaGetSymbolAddress((void**)&h, g_h);
    cudaGetSymbolAddress((void**)&h3, g_h3);
    __nv_bfloat16 *abh, *abl, *w1h, *w1l, *w2h, *w2l, *w3h, *w3l;
    cudaGetSymbolAddress((void**)&abh, g_abh);
    cudaGetSymbolAddress((void**)&abl, g_abl);
    cudaGetSymbolAddress((void**)&w1h, g_w1h);
    cudaGetSymbolAddress((void**)&w1l, g_w1l);
    cudaGetSymbolAddress((void**)&w2h, g_w2h);
    cudaGetSymbolAddress((void**)&w2l, g_w2l);
    cudaGetSymbolAddress((void**)&w3h, g_w3h);
    cudaGetSymbolAddress((void**)&w3l, g_w3l);

    const int NB_NODE = (N_NODES + 255) / 256;     // 391
    const int NB_EDGE = (N_EDGES + 255) / 256;
    const int NB_GEMM = (N_NODES + 127) / 128;     // 782
    const int NB_AGG128 = (N_NODES + 7) / 8;       // 12500
    const int NB_AGG64 = (N_NODES + 15) / 16;      // 6250
    const int NB_DEC = (N_EDGES * 16) / 256;       // 31250

    prep_weights_kernel<<<64, 256>>>(W1, W2, W3);

    for (int net = 0; net < 2; net++) {
        const float* x = net ? xt : xs;
        const __nv_bfloat16* wah = net ? w2h : w1h;
        const __nv_bfloat16* wal = net ? w2l : w1l;
        const float* ba = net ? b2 : b1;
        const int* src = net ? t_ei : s_ei;
        const int* dst = src + N_EDGES;
        float* zout = net ? zt : zs;

        // degree + CSR (shared by both convs of this network)
        deg_init_kernel<<<NB_NODE, 256>>>();
        deg_count_kernel<<<NB_EDGE, 256>>>(dst);
        deg_finish_kernel<<<NB_NODE, 256>>>();
        scan1_kernel<<<NB_NODE, 256>>>();
        scan2_kernel<<<1, 512>>>(NB_NODE);
        scan3_kernel<<<NB_NODE, 256>>>();
        csr_fill_kernel<<<NB_EDGE, 256>>>(src, dst);

        // layer 1: h = x@W ; agg (fused bias+relu+bf16 split)
        gemm_mma_kernel<128, true><<<NB_GEMM, 256>>>(x, nullptr, nullptr, wah, wal, h, N_NODES);
        agg128_kernel<<<NB_AGG128, 256>>>(h, ba);

        // layer 2 (shared W3): h3 = relu_h@W3 ; agg (fused +b3) -> z
        gemm_mma_kernel<64, false><<<NB_GEMM, 256>>>(nullptr, abh, abl, w3h, w3l, h3, N_NODES);
        agg64_kernel<<<NB_AGG64, 256>>>(h3, b3, zout);
    }

    decoder_kernel<<<NB_DEC, 256>>>(zs, s_ei, s_ei + N_EDGES, ps);
    decoder_kernel<<<NB_DEC, 256>>>(zt, t_ei, t_ei + N_EDGES, pt);
}

// round 5
// speedup vs baseline: 1.7155x; 1.0683x over previous
#include <cuda_runtime.h>
#include <cuda_bf16.h>
#include <math.h>
#include <stdint.h>

#define N_NODES 100000
#define N_EDGES 500000
#define N2 (2 * N_NODES)      // 200000
#define E2 (2 * N_EDGES)      // 1000000
#define NB1 782               // gemm blocks per net (ceil(100000/128))

// ---------------- scratch (static device globals; no allocation) ----------------
__device__ float g_h[(size_t)N2 * 128];        // layer1 conv output, both nets
__device__ float g_h3[(size_t)N2 * 64];        // layer2 conv output, both nets
__device__ float g_dis[N2];
__device__ float g_invdeg[N2];
__device__ int g_cnt[N2];
__device__ int g_rowstart[N2 + 1];
__device__ int g_cursor[N2];
__device__ int g_blocksums[1024];
__device__ int g_csr_src[E2];                  // global rows (net*N + s)
__device__ float g_csr_norm[E2];
__device__ __nv_bfloat16 g_abh[(size_t)N2 * 128];
__device__ __nv_bfloat16 g_abl[(size_t)N2 * 128];
__device__ __nv_bfloat16 g_w1h[128 * 128], g_w1l[128 * 128];
__device__ __nv_bfloat16 g_w2h[128 * 128], g_w2l[128 * 128];
__device__ __nv_bfloat16 g_w3h[64 * 128],  g_w3l[64 * 128];

__device__ __forceinline__ uint32_t smem_u32(const void* p) {
    uint32_t a;
    asm("{ .reg .u64 t; cvta.to.shared.u64 t, %1; cvt.u32.u64 %0, t; }" : "=r"(a) : "l"(p));
    return a;
}
__device__ __forceinline__ void split_bf16(float v, __nv_bfloat16& hi, __nv_bfloat16& lo) {
    hi = __float2bfloat16_rn(v);
    lo = __float2bfloat16_rn(v - __bfloat162float(hi));
}

// ---------------- degree + CSR build (both nets concatenated) ----------------
__global__ void deg_count_both(const int* __restrict__ s_ei, const int* __restrict__ t_ei) {
    int g = blockIdx.x * blockDim.x + threadIdx.x;
    if (g >= E2) return;
    int net = (g >= N_EDGES);
    int e = g - net * N_EDGES;
    const int* ei = net ? t_ei : s_ei;
    int d = ei[N_EDGES + e];
    atomicAdd(&g_cnt[net * N_NODES + d], 1);
}

// block scan + deg finish fused
__global__ void scan1_kernel() {
    __shared__ int s[2][256];
    int tid = threadIdx.x;
    int i = blockIdx.x * 256 + tid;
    int v = (i < N2) ? g_cnt[i] : 0;
    if (i < N2) {
        float d = (float)v + 1.0f;
        g_dis[i] = rsqrtf(d);
        g_invdeg[i] = 1.0f / d;
    }
    int buf = 0;
    s[0][tid] = v;
    __syncthreads();
#pragma unroll
    for (int off = 1; off < 256; off <<= 1) {
        int nb = buf ^ 1;
        s[nb][tid] = s[buf][tid] + (tid >= off ? s[buf][tid - off] : 0);
        buf = nb;
        __syncthreads();
    }
    if (i < N2) g_rowstart[i] = s[buf][tid] - v;
    if (tid == 255) g_blocksums[blockIdx.x] = s[buf][255];
}
__global__ void scan2_kernel(int nblocks) {
    __shared__ int s[2][1024];
    int tid = threadIdx.x;
    int v = (tid < nblocks) ? g_blocksums[tid] : 0;
    int buf = 0;
    s[0][tid] = v;
    __syncthreads();
#pragma unroll
    for (int off = 1; off < 1024; off <<= 1) {
        int nb = buf ^ 1;
        s[nb][tid] = s[buf][tid] + (tid >= off ? s[buf][tid - off] : 0);
        buf = nb;
        __syncthreads();
    }
    g_blocksums[tid] = s[buf][tid] - v;
}
__global__ void scan3_kernel() {
    int i = blockIdx.x * blockDim.x + threadIdx.x;
    if (i < N2) {
        g_rowstart[i] += g_blocksums[i >> 8];
        g_cursor[i] = 0;
    }
    if (i == 0) g_rowstart[N2] = E2;
}
__global__ void csr_fill_both(const int* __restrict__ s_ei, const int* __restrict__ t_ei) {
    int g = blockIdx.x * blockDim.x + threadIdx.x;
    if (g >= E2) return;
    int net = (g >= N_EDGES);
    int e = g - net * N_EDGES;
    const int* ei = net ? t_ei : s_ei;
    int s = net * N_NODES + ei[e];
    int d = net * N_NODES + ei[N_EDGES + e];
    int pos = g_rowstart[d] + atomicAdd(&g_cursor[d], 1);
    g_csr_src[pos] = s;
    g_csr_norm[pos] = g_dis[s] * g_dis[d];
}

// ---------------- weight prep ----------------
__global__ void prep_weights_kernel(const float* __restrict__ W1, const float* __restrict__ W2,
                                    const float* __restrict__ W3) {
    int tid = blockIdx.x * blockDim.x + threadIdx.x;
    if (tid < 128 * 128) {
        int n = tid >> 7, k = tid & 127;
        __nv_bfloat16 hi, lo;
        split_bf16(W1[k * 128 + n], hi, lo);
        g_w1h[n * 128 + k] = hi; g_w1l[n * 128 + k] = lo;
        split_bf16(W2[k * 128 + n], hi, lo);
        g_w2h[n * 128 + k] = hi; g_w2l[n * 128 + k] = lo;
        if (n < 64) {
            split_bf16(W3[k * 64 + n], hi, lo);
            g_w3h[n * 128 + k] = hi; g_w3l[n * 128 + k] = lo;
        }
    }
}

// ---------------- bf16-split HMMA GEMM core ----------------
#define SKP 40

// layer1: both nets in one launch (BN=128, A fp32 per-net)
__global__ void __launch_bounds__(256) gemm1_both(
        const float* __restrict__ xs, const float* __restrict__ xt) {
    constexpr int BN = 128, NT = 8;
    __shared__ __nv_bfloat16 sAh[128][SKP];
    __shared__ __nv_bfloat16 sAl[128][SKP];
    __shared__ __nv_bfloat16 sBh[BN][SKP];
    __shared__ __nv_bfloat16 sBl[BN][SKP];

    const int tid = threadIdx.x;
    const int wid = tid >> 5, lane = tid & 31;
    const int warp_m = (wid & 3) * 32;
    const int warp_n = (wid >> 2) * 64;
    const int net = (blockIdx.x >= NB1);
    const int m0 = (blockIdx.x - net * NB1) * 128;
    const float* Af = net ? xt : xs;
    const __nv_bfloat16* Bh_g = net ? g_w2h : g_w1h;
    const __nv_bfloat16* Bl_g = net ? g_w2l : g_w1l;
    float* Ch = g_h + (size_t)net * N_NODES * 128;

    float acc[2][NT][4];
#pragma unroll
    for (int mt = 0; mt < 2; mt++)
#pragma unroll
        for (int nt = 0; nt < NT; nt++)
#pragma unroll
            for (int r = 0; r < 4; r++) acc[mt][nt][r] = 0.0f;

    const uint32_t sAh_b = smem_u32(&sAh[0][0]);
    const uint32_t sAl_b = smem_u32(&sAl[0][0]);
    const uint32_t sBh_b = smem_u32(&sBh[0][0]);
    const uint32_t sBl_b = smem_u32(&sBl[0][0]);
    const int a_row = warp_m + (lane & 15);
    const int a_khalf = (lane >> 4) << 3;
    const int b_row = warp_n + (lane & 7);
    const int b_khalf = lane & 8;

    for (int k0 = 0; k0 < 128; k0 += 32) {
#pragma unroll
        for (int it = 0; it < 4; it++) {
            int i = tid + it * 256;
            int r = i >> 3, c = (i & 7) * 4;
            float4 v = make_float4(0.f, 0.f, 0.f, 0.f);
            if (m0 + r < N_NODES) v = *(const float4*)&Af[(size_t)(m0 + r) * 128 + k0 + c];
            __nv_bfloat16 h0, h1, h2, h3, l0, l1, l2, l3;
            split_bf16(v.x, h0, l0); split_bf16(v.y, h1, l1);
            split_bf16(v.z, h2, l2); split_bf16(v.w, h3, l3);
            __nv_bfloat162 ph0 = {h0, h1}, ph1 = {h2, h3};
            __nv_bfloat162 pl0 = {l0, l1}, pl1 = {l2, l3};
            *(uint2*)&sAh[r][c] = make_uint2(*(uint32_t*)&ph0, *(uint32_t*)&ph1);
            *(uint2*)&sAl[r][c] = make_uint2(*(uint32_t*)&pl0, *(uint32_t*)&pl1);
        }
#pragma unroll
        for (int it = 0; it < 2; it++) {
            int i = tid + it * 256;
            int r = i >> 2, q = i & 3;
            *(uint4*)&sBh[r][q * 8] = *(const uint4*)&Bh_g[r * 128 + k0 + q * 8];
            *(uint4*)&sBl[r][q * 8] = *(const uint4*)&Bl_g[r * 128 + k0 + q * 8];
        }
        __syncthreads();
#pragma unroll
        for (int pass = 0; pass < 3; pass++) {
            const uint32_t aBase = (pass < 2) ? sAh_b : sAl_b;
            const uint32_t bBase = (pass == 1) ? sBl_b : sBh_b;
#pragma unroll
            for (int ks = 0; ks < 2; ks++) {
                uint32_t af[2][4];
#pragma unroll
                for (int mt = 0; mt < 2; mt++) {
                    uint32_t addr = aBase + ((a_row + mt * 16) * SKP + ks * 16 + a_khalf) * 2;
                    asm volatile("ldmatrix.sync.aligned.m8n8.x4.shared.b16 {%0,%1,%2,%3}, [%4];"
                        : "=r"(af[mt][0]), "=r"(af[mt][1]), "=r"(af[mt][2]), "=r"(af[mt][3])
                        : "r"(addr));
                }
#pragma unroll
                for (int nt = 0; nt < NT; nt++) {
                    uint32_t b0, b1;
                    uint32_t addr = bBase + ((b_row + nt * 8) * SKP + ks * 16 + b_khalf) * 2;
                    asm volatile("ldmatrix.sync.aligned.m8n8.x2.shared.b16 {%0,%1}, [%2];"
                        : "=r"(b0), "=r"(b1) : "r"(addr));
#pragma unroll
                    for (int mt = 0; mt < 2; mt++) {
                        asm volatile(
                            "mma.sync.aligned.m16n8k16.row.col.f32.bf16.bf16.f32 "
                            "{%0,%1,%2,%3}, {%4,%5,%6,%7}, {%8,%9}, {%0,%1,%2,%3};"
                            : "+f"(acc[mt][nt][0]), "+f"(acc[mt][nt][1]),
                              "+f"(acc[mt][nt][2]), "+f"(acc[mt][nt][3])
                            : "r"(af[mt][0]), "r"(af[mt][1]), "r"(af[mt][2]), "r"(af[mt][3]),
                              "r"(b0), "r"(b1));
                    }
                }
            }
        }
        __syncthreads();
    }
#pragma unroll
    for (int mt = 0; mt < 2; mt++) {
        int r0 = m0 + warp_m + mt * 16 + (lane >> 2);
        int r1 = r0 + 8;
#pragma unroll
        for (int nt = 0; nt < NT; nt++) {
            int n0 = warp_n + nt * 8 + 2 * (lane & 3);
            if (r0 < N_NODES)
                *(float2*)&Ch[(size_t)r0 * 128 + n0] = make_float2(acc[mt][nt][0], acc[mt][nt][1]);
            if (r1 < N_NODES)
                *(float2*)&Ch[(size_t)r1 * 128 + n0] = make_float2(acc[mt][nt][2], acc[mt][nt][3]);
        }
    }
}

// layer2: single GEMM over M=200000 (shared W3), A pre-split bf16
__global__ void __launch_bounds__(256) gemm2_both() {
    constexpr int BN = 64, NT = 4;
    __shared__ __nv_bfloat16 sAh[128][SKP];
    __shared__ __nv_bfloat16 sAl[128][SKP];
    __shared__ __nv_bfloat16 sBh[BN][SKP];
    __shared__ __nv_bfloat16 sBl[BN][SKP];

    const int tid = threadIdx.x;
    const int wid = tid >> 5, lane = tid & 31;
    const int warp_m = (wid & 3) * 32;
    const int warp_n = (wid >> 2) * 32;
    const int m0 = blockIdx.x * 128;

    float acc[2][NT][4];
#pragma unroll
    for (int mt = 0; mt < 2; mt++)
#pragma unroll
        for (int nt = 0; nt < NT; nt++)
#pragma unroll
            for (int r = 0; r < 4; r++) acc[mt][nt][r] = 0.0f;

    const uint32_t sAh_b = smem_u32(&sAh[0][0]);
    const uint32_t sAl_b = smem_u32(&sAl[0][0]);
    const uint32_t sBh_b = smem_u32(&sBh[0][0]);
    const uint32_t sBl_b = smem_u32(&sBl[0][0]);
    const int a_row = warp_m + (lane & 15);
    const int a_khalf = (lane >> 4) << 3;
    const int b_row = warp_n + (lane & 7);
    const int b_khalf = lane & 8;

    for (int k0 = 0; k0 < 128; k0 += 32) {
#pragma unroll
        for (int it = 0; it < 2; it++) {
            int i = tid + it * 256;
            int r = i >> 2, q = i & 3;
            uint4 vh = make_uint4(0, 0, 0, 0), vl = make_uint4(0, 0, 0, 0);
            if (m0 + r < N2) {
                vh = *(const uint4*)&g_abh[(size_t)(m0 + r) * 128 + k0 + q * 8];
                vl = *(const uint4*)&g_abl[(size_t)(m0 + r) * 128 + k0 + q * 8];
            }
            *(uint4*)&sAh[r][q * 8] = vh;
            *(uint4*)&sAl[r][q * 8] = vl;
        }
        {
            int i = tid;   // 256 uint4 for BN=64
            int r = i >> 2, q = i & 3;
            *(uint4*)&sBh[r][q * 8] = *(const uint4*)&g_w3h[r * 128 + k0 + q * 8];
            *(uint4*)&sBl[r][q * 8] = *(const uint4*)&g_w3l[r * 128 + k0 + q * 8];
        }
        __syncthreads();
#pragma unroll
        for (int pass = 0; pass < 3; pass++) {
            const uint32_t aBase = (pass < 2) ? sAh_b : sAl_b;
            const uint32_t bBase = (pass == 1) ? sBl_b : sBh_b;
#pragma unroll
            for (int ks = 0; ks < 2; ks++) {
                uint32_t af[2][4];
#pragma unroll
                for (int mt = 0; mt < 2; mt++) {
                    uint32_t addr = aBase + ((a_row + mt * 16) * SKP + ks * 16 + a_khalf) * 2;
                    asm volatile("ldmatrix.sync.aligned.m8n8.x4.shared.b16 {%0,%1,%2,%3}, [%4];"
                        : "=r"(af[mt][0]), "=r"(af[mt][1]), "=r"(af[mt][2]), "=r"(af[mt][3])
                        : "r"(addr));
                }
#pragma unroll
                for (int nt = 0; nt < NT; nt++) {
                    uint32_t b0, b1;
                    uint32_t addr = bBase + ((b_row + nt * 8) * SKP + ks * 16 + b_khalf) * 2;
                    asm volatile("ldmatrix.sync.aligned.m8n8.x2.shared.b16 {%0,%1}, [%2];"
                        : "=r"(b0), "=r"(b1) : "r"(addr));
#pragma unroll
                    for (int mt = 0; mt < 2; mt++) {
                        asm volatile(
                            "mma.sync.aligned.m16n8k16.row.col.f32.bf16.bf16.f32 "
                            "{%0,%1,%2,%3}, {%4,%5,%6,%7}, {%8,%9}, {%0,%1,%2,%3};"
                            : "+f"(acc[mt][nt][0]), "+f"(acc[mt][nt][1]),
                              "+f"(acc[mt][nt][2]), "+f"(acc[mt][nt][3])
                            : "r"(af[mt][0]), "r"(af[mt][1]), "r"(af[mt][2]), "r"(af[mt][3]),
                              "r"(b0), "r"(b1));
                    }
                }
            }
        }
        __syncthreads();
    }
#pragma unroll
    for (int mt = 0; mt < 2; mt++) {
        int r0 = m0 + warp_m + mt * 16 + (lane >> 2);
        int r1 = r0 + 8;
#pragma unroll
        for (int nt = 0; nt < NT; nt++) {
            int n0 = warp_n + nt * 8 + 2 * (lane & 3);
            if (r0 < N2)
                *(float2*)&g_h3[(size_t)r0 * 64 + n0] = make_float2(acc[mt][nt][0], acc[mt][nt][1]);
            if (r1 < N2)
                *(float2*)&g_h3[(size_t)r1 * 64 + n0] = make_float2(acc[mt][nt][2], acc[mt][nt][3]);
        }
    }
}

// ---------------- CSR aggregation C=128, both nets; fused bias+relu+bf16 split ----------------
__global__ void __launch_bounds__(256) agg128_both(const float* __restrict__ b1,
                                                   const float* __restrict__ b2) {
    int node = blockIdx.x * 8 + (threadIdx.x >> 5);     // global row [0, 2N)
    int lane = threadIdx.x & 31;
    if (node >= N2) return;
    float inv = g_invdeg[node];
    float4 acc = *(const float4*)&g_h[(size_t)node * 128 + lane * 4];
    acc.x *= inv; acc.y *= inv; acc.z *= inv; acc.w *= inv;
    int i = g_rowstart[node], end = g_rowstart[node + 1];
    for (; i + 1 < end; i += 2) {
        int s0 = g_csr_src[i], s1 = g_csr_src[i + 1];
        float n0 = g_csr_norm[i], n1 = g_csr_norm[i + 1];
        float4 v0 = *(const float4*)&g_h[(size_t)s0 * 128 + lane * 4];
        float4 v1 = *(const float4*)&g_h[(size_t)s1 * 128 + lane * 4];
        acc.x = fmaf(v0.x, n0, fmaf(v1.x, n1, acc.x));
        acc.y = fmaf(v0.y, n0, fmaf(v1.y, n1, acc.y));
        acc.z = fmaf(v0.z, n0, fmaf(v1.z, n1, acc.z));
        acc.w = fmaf(v0.w, n0, fmaf(v1.w, n1, acc.w));
    }
    if (i < end) {
        int s0 = g_csr_src[i];
        float n0 = g_csr_norm[i];
        float4 v0 = *(const float4*)&g_h[(size_t)s0 * 128 + lane * 4];
        acc.x = fmaf(v0.x, n0, acc.x);
        acc.y = fmaf(v0.y, n0, acc.y);
        acc.z = fmaf(v0.z, n0, acc.z);
        acc.w = fmaf(v0.w, n0, acc.w);
    }
    const float* b = (node >= N_NODES) ? b2 : b1;
    float4 bb = ((const float4*)b)[lane];
    acc.x = fmaxf(acc.x + bb.x, 0.f); acc.y = fmaxf(acc.y + bb.y, 0.f);
    acc.z = fmaxf(acc.z + bb.z, 0.f); acc.w = fmaxf(acc.w + bb.w, 0.f);
    __nv_bfloat16 h0, h1, h2, h3, l0, l1, l2, l3;
    split_bf16(acc.x, h0, l0); split_bf16(acc.y, h1, l1);
    split_bf16(acc.z, h2, l2); split_bf16(acc.w, h3, l3);
    __nv_bfloat162 ph0 = {h0, h1}, ph1 = {h2, h3}, pl0 = {l0, l1}, pl1 = {l2, l3};
    size_t idx = (size_t)node * 32 + lane;
    ((uint2*)g_abh)[idx] = make_uint2(*(uint32_t*)&ph0, *(uint32_t*)&ph1);
    ((uint2*)g_abl)[idx] = make_uint2(*(uint32_t*)&pl0, *(uint32_t*)&pl1);
}

// ---------------- CSR aggregation C=64, both nets; fused +b3 -> zs|zt ----------------
__global__ void __launch_bounds__(256) agg64_both(const float* __restrict__ b3,
                                                  float* __restrict__ out) {
    int node = blockIdx.x * 16 + (threadIdx.x >> 4);
    int l = threadIdx.x & 15;
    if (node >= N2) return;
    float inv = g_invdeg[node];
    float4 acc = *(const float4*)&g_h3[(size_t)node * 64 + l * 4];
    acc.x *= inv; acc.y *= inv; acc.z *= inv; acc.w *= inv;
    int i = g_rowstart[node], end = g_rowstart[node + 1];
    for (; i + 1 < end; i += 2) {
        int s0 = g_csr_src[i], s1 = g_csr_src[i + 1];
        float n0 = g_csr_norm[i], n1 = g_csr_norm[i + 1];
        float4 v0 = *(const float4*)&g_h3[(size_t)s0 * 64 + l * 4];
        float4 v1 = *(const float4*)&g_h3[(size_t)s1 * 64 + l * 4];
        acc.x = fmaf(v0.x, n0, fmaf(v1.x, n1, acc.x));
        acc.y = fmaf(v0.y, n0, fmaf(v1.y, n1, acc.y));
        acc.z = fmaf(v0.z, n0, fmaf(v1.z, n1, acc.z));
        acc.w = fmaf(v0.w, n0, fmaf(v1.w, n1, acc.w));
    }
    if (i < end) {
        int s0 = g_csr_src[i];
        float n0 = g_csr_norm[i];
        float4 v0 = *(const float4*)&g_h3[(size_t)s0 * 64 + l * 4];
        acc.x = fmaf(v0.x, n0, acc.x);
        acc.y = fmaf(v0.y, n0, acc.y);
        acc.z = fmaf(v0.z, n0, acc.z);
        acc.w = fmaf(v0.w, n0, acc.w);
    }
    float4 bb = ((const float4*)b3)[l];
    acc.x += bb.x; acc.y += bb.y; acc.z += bb.z; acc.w += bb.w;
    *(float4*)&out[(size_t)node * 64 + l * 4] = acc;   // zs|zt contiguous
}

// ---------------- decoder, both nets ----------------
__global__ void decoder_both(const float* __restrict__ z, const int* __restrict__ s_ei,
                             const int* __restrict__ t_ei, float* __restrict__ p) {
    int gtid = blockIdx.x * blockDim.x + threadIdx.x;
    int eg = gtid >> 4;                 // [0, 2E)
    int l = gtid & 15;
    if (eg >= E2) return;
    int net = (eg >= N_EDGES);
    int e = eg - net * N_EDGES;
    const int* ei = net ? t_ei : s_ei;
    int base = net * N_NODES;
    int s = base + ei[e];
    int d = base + ei[N_EDGES + e];
    float4 a = *(const float4*)&z[(size_t)s * 64 + l * 4];
    float4 b = *(const float4*)&z[(size_t)d * 64 + l * 4];
    float v = a.x * b.x + a.y * b.y + a.z * b.z + a.w * b.w;
    v += __shfl_xor_sync(0xffffffffu, v, 8);
    v += __shfl_xor_sync(0xffffffffu, v, 4);
    v += __shfl_xor_sync(0xffffffffu, v, 2);
    v += __shfl_xor_sync(0xffffffffu, v, 1);
    if (l == 0) p[eg] = 1.0f / (1.0f + expf(-v));   // ps|pt contiguous
}

// ---------------- launch ----------------
extern "C" void kernel_launch(void* const* d_in, const int* in_sizes, int n_in,
                              void* d_out, int out_size) {
    const float* xs = (const float*)d_in[0];
    const float* xt = (const float*)d_in[1];
    const int* s_ei = (const int*)d_in[2];
    const int* t_ei = (const int*)d_in[3];
    const float* W1 = (const float*)d_in[4];
    const float* b1 = (const float*)d_in[5];
    const float* W2 = (const float*)d_in[6];
    const float* b2 = (const float*)d_in[7];
    const float* W3 = (const float*)d_in[8];
    const float* b3 = (const float*)d_in[9];

    float* out = (float*)d_out;
    float* z = out;                               // zs|zt [2N,64]
    float* p = out + (size_t)N2 * 64;             // ps|pt [2E]

    int* cnt;
    cudaGetSymbolAddress((void**)&cnt, g_cnt);

    const int NB_N2 = (N2 + 255) / 256;           // 782
    const int NB_E2 = (E2 + 255) / 256;           // 3907
    const int NB_G2 = (N2 + 127) / 128;           // 1563
    const int NB_A128 = (N2 + 7) / 8;             // 25000
    const int NB_A64 = (N2 + 15) / 16;            // 12500
    const int NB_DEC = (E2 * 16 + 255) / 256;     // 62500

    prep_weights_kernel<<<64, 256>>>(W1, W2, W3);
    cudaMemsetAsync(cnt, 0, N2 * sizeof(int));
    deg_count_both<<<NB_E2, 256>>>(s_ei, t_ei);
    scan1_kernel<<<NB_N2, 256>>>();
    scan2_kernel<<<1, 1024>>>(NB_N2);
    scan3_kernel<<<NB_N2, 256>>>();
    csr_fill_both<<<NB_E2, 256>>>(s_ei, t_ei);

    gemm1_both<<<2 * NB1, 256>>>(xs, xt);
    agg128_both<<<NB_A128, 256>>>(b1, b2);
    gemm2_both<<<NB_G2, 256>>>();
    agg64_both<<<NB_A64, 256>>>(b3, z);

    decoder_both<<<NB_DEC, 256>>>(z, s_ei, t_ei, p);
}

// round 7
// speedup vs baseline: 1.7551x; 1.0231x over previous
#include <cuda_runtime.h>
#include <cuda_bf16.h>
#include <math.h>
#include <stdint.h>

#define N_NODES 100000
#define N_EDGES 500000
#define N2 (2 * N_NODES)      // 200000
#define E2 (2 * N_EDGES)      // 1000000
#define NB1 782               // gemm blocks per net (ceil(100000/128))

// ---------------- scratch (static device globals; no allocation) ----------------
__device__ float g_h[(size_t)N2 * 128];        // layer1 conv output, both nets
__device__ float g_h3[(size_t)N2 * 64];        // layer2 conv output, both nets
__device__ float g_dis[N2];
__device__ float g_invdeg[N2];
__device__ int g_cnt[N2];
__device__ int g_rowstart[N2 + 1];
__device__ int g_cursor[N2];
__device__ int g_blocksums[1024];
__device__ int g_csr_src[E2];                  // global rows (net*N + s)
__device__ float g_csr_norm[E2];
__device__ __nv_bfloat16 g_abh[(size_t)N2 * 128];
__device__ __nv_bfloat16 g_abl[(size_t)N2 * 128];
__device__ __nv_bfloat16 g_w1h[128 * 128], g_w1l[128 * 128];
__device__ __nv_bfloat16 g_w2h[128 * 128], g_w2l[128 * 128];
__device__ __nv_bfloat16 g_w3h[64 * 128],  g_w3l[64 * 128];

// ---------------- pre-created side stream + events (static init; NOT during capture) ----
struct SideStream {
    cudaStream_t s;
    cudaEvent_t ev_fork, ev_join;
    SideStream() {
        cudaStreamCreateWithFlags(&s, cudaStreamNonBlocking);
        cudaEventCreateWithFlags(&ev_fork, cudaEventDisableTiming);
        cudaEventCreateWithFlags(&ev_join, cudaEventDisableTiming);
    }
};
static SideStream g_side;

__device__ __forceinline__ uint32_t smem_u32(const void* p) {
    uint32_t a;
    asm("{ .reg .u64 t; cvta.to.shared.u64 t, %1; cvt.u32.u64 %0, t; }" : "=r"(a) : "l"(p));
    return a;
}
__device__ __forceinline__ void split_bf16(float v, __nv_bfloat16& hi, __nv_bfloat16& lo) {
    hi = __float2bfloat16_rn(v);
    lo = __float2bfloat16_rn(v - __bfloat162float(hi));
}

// ---------------- degree + CSR build (both nets concatenated) ----------------
__global__ void deg_count_both(const int* __restrict__ s_ei, const int* __restrict__ t_ei) {
    int g = blockIdx.x * blockDim.x + threadIdx.x;
    if (g >= E2) return;
    int net = (g >= N_EDGES);
    int e = g - net * N_EDGES;
    const int* ei = net ? t_ei : s_ei;
    int d = ei[N_EDGES + e];
    atomicAdd(&g_cnt[net * N_NODES + d], 1);
}

// block scan + deg finish fused
__global__ void scan1_kernel() {
    __shared__ int s[2][256];
    int tid = threadIdx.x;
    int i = blockIdx.x * 256 + tid;
    int v = (i < N2) ? g_cnt[i] : 0;
    if (i < N2) {
        float d = (float)v + 1.0f;
        g_dis[i] = rsqrtf(d);
        g_invdeg[i] = 1.0f / d;
    }
    int buf = 0;
    s[0][tid] = v;
    __syncthreads();
#pragma unroll
    for (int off = 1; off < 256; off <<= 1) {
        int nb = buf ^ 1;
        s[nb][tid] = s[buf][tid] + (tid >= off ? s[buf][tid - off] : 0);
        buf = nb;
        __syncthreads();
    }
    if (i < N2) g_rowstart[i] = s[buf][tid] - v;
    if (tid == 255) g_blocksums[blockIdx.x] = s[buf][255];
}
__global__ void scan2_kernel(int nblocks) {
    __shared__ int s[2][1024];
    int tid = threadIdx.x;
    int v = (tid < nblocks) ? g_blocksums[tid] : 0;
    int buf = 0;
    s[0][tid] = v;
    __syncthreads();
#pragma unroll
    for (int off = 1; off < 1024; off <<= 1) {
        int nb = buf ^ 1;
        s[nb][tid] = s[buf][tid] + (tid >= off ? s[buf][tid - off] : 0);
        buf = nb;
        __syncthreads();
    }
    g_blocksums[tid] = s[buf][tid] - v;
}
__global__ void scan3_kernel() {
    int i = blockIdx.x * blockDim.x + threadIdx.x;
    if (i < N2) {
        g_rowstart[i] += g_blocksums[i >> 8];
        g_cursor[i] = 0;
    }
    if (i == 0) g_rowstart[N2] = E2;
}
__global__ void csr_fill_both(const int* __restrict__ s_ei, const int* __restrict__ t_ei) {
    int g = blockIdx.x * blockDim.x + threadIdx.x;
    if (g >= E2) return;
    int net = (g >= N_EDGES);
    int e = g - net * N_EDGES;
    const int* ei = net ? t_ei : s_ei;
    int s = net * N_NODES + ei[e];
    int d = net * N_NODES + ei[N_EDGES + e];
    int pos = g_rowstart[d] + atomicAdd(&g_cursor[d], 1);
    g_csr_src[pos] = s;
    g_csr_norm[pos] = g_dis[s] * g_dis[d];
}

// ---------------- weight prep ----------------
__global__ void prep_weights_kernel(const float* __restrict__ W1, const float* __restrict__ W2,
                                    const float* __restrict__ W3) {
    int tid = blockIdx.x * blockDim.x + threadIdx.x;
    if (tid < 128 * 128) {
        int n = tid >> 7, k = tid & 127;
        __nv_bfloat16 hi, lo;
        split_bf16(W1[k * 128 + n], hi, lo);
        g_w1h[n * 128 + k] = hi; g_w1l[n * 128 + k] = lo;
        split_bf16(W2[k * 128 + n], hi, lo);
        g_w2h[n * 128 + k] = hi; g_w2l[n * 128 + k] = lo;
        if (n < 64) {
            split_bf16(W3[k * 64 + n], hi, lo);
            g_w3h[n * 128 + k] = hi; g_w3l[n * 128 + k] = lo;
        }
    }
}

// ---------------- bf16-split HMMA GEMM core ----------------
#define SKP 40

// layer1: both nets in one launch (BN=128, A fp32 per-net)
__global__ void __launch_bounds__(256) gemm1_both(
        const float* __restrict__ xs, const float* __restrict__ xt) {
    constexpr int NT = 8;
    __shared__ __nv_bfloat16 sAh[128][SKP];
    __shared__ __nv_bfloat16 sAl[128][SKP];
    __shared__ __nv_bfloat16 sBh[128][SKP];
    __shared__ __nv_bfloat16 sBl[128][SKP];

    const int tid = threadIdx.x;
    const int wid = tid >> 5, lane = tid & 31;
    const int warp_m = (wid & 3) * 32;
    const int warp_n = (wid >> 2) * 64;
    const int net = (blockIdx.x >= NB1);
    const int m0 = (blockIdx.x - net * NB1) * 128;
    const float* Af = net ? xt : xs;
    const __nv_bfloat16* Bh_g = net ? g_w2h : g_w1h;
    const __nv_bfloat16* Bl_g = net ? g_w2l : g_w1l;
    float* Ch = g_h + (size_t)net * N_NODES * 128;

    float acc[2][NT][4];
#pragma unroll
    for (int mt = 0; mt < 2; mt++)
#pragma unroll
        for (int nt = 0; nt < NT; nt++)
#pragma unroll
            for (int r = 0; r < 4; r++) acc[mt][nt][r] = 0.0f;

    const uint32_t sAh_b = smem_u32(&sAh[0][0]);
    const uint32_t sAl_b = smem_u32(&sAl[0][0]);
    const uint32_t sBh_b = smem_u32(&sBh[0][0]);
    const uint32_t sBl_b = smem_u32(&sBl[0][0]);
    const int a_row = warp_m + (lane & 15);
    const int a_khalf = (lane >> 4) << 3;
    const int b_row = warp_n + (lane & 7);
    const int b_khalf = lane & 8;

    for (int k0 = 0; k0 < 128; k0 += 32) {
#pragma unroll
        for (int it = 0; it < 4; it++) {
            int i = tid + it * 256;
            int r = i >> 3, c = (i & 7) * 4;
            float4 v = make_float4(0.f, 0.f, 0.f, 0.f);
            if (m0 + r < N_NODES) v = *(const float4*)&Af[(size_t)(m0 + r) * 128 + k0 + c];
            __nv_bfloat16 h0, h1, h2, h3, l0, l1, l2, l3;
            split_bf16(v.x, h0, l0); split_bf16(v.y, h1, l1);
            split_bf16(v.z, h2, l2); split_bf16(v.w, h3, l3);
            __nv_bfloat162 ph0 = {h0, h1}, ph1 = {h2, h3};
            __nv_bfloat162 pl0 = {l0, l1}, pl1 = {l2, l3};
            *(uint2*)&sAh[r][c] = make_uint2(*(uint32_t*)&ph0, *(uint32_t*)&ph1);
            *(uint2*)&sAl[r][c] = make_uint2(*(uint32_t*)&pl0, *(uint32_t*)&pl1);
        }
#pragma unroll
        for (int it = 0; it < 2; it++) {
            int i = tid + it * 256;
            int r = i >> 2, q = i & 3;
            *(uint4*)&sBh[r][q * 8] = *(const uint4*)&Bh_g[r * 128 + k0 + q * 8];
            *(uint4*)&sBl[r][q * 8] = *(const uint4*)&Bl_g[r * 128 + k0 + q * 8];
        }
        __syncthreads();
#pragma unroll
        for (int pass = 0; pass < 3; pass++) {
            const uint32_t aBase = (pass < 2) ? sAh_b : sAl_b;
            const uint32_t bBase = (pass == 1) ? sBl_b : sBh_b;
#pragma unroll
            for (int ks = 0; ks < 2; ks++) {
                uint32_t af[2][4];
#pragma unroll
                for (int mt = 0; mt < 2; mt++) {
                    uint32_t addr = aBase + ((a_row + mt * 16) * SKP + ks * 16 + a_khalf) * 2;
                    asm volatile("ldmatrix.sync.aligned.m8n8.x4.shared.b16 {%0,%1,%2,%3}, [%4];"
                        : "=r"(af[mt][0]), "=r"(af[mt][1]), "=r"(af[mt][2]), "=r"(af[mt][3])
                        : "r"(addr));
                }
#pragma unroll
                for (int nt = 0; nt < NT; nt++) {
                    uint32_t b0, b1;
                    uint32_t addr = bBase + ((b_row + nt * 8) * SKP + ks * 16 + b_khalf) * 2;
                    asm volatile("ldmatrix.sync.aligned.m8n8.x2.shared.b16 {%0,%1}, [%2];"
                        : "=r"(b0), "=r"(b1) : "r"(addr));
#pragma unroll
                    for (int mt = 0; mt < 2; mt++) {
                        asm volatile(
                            "mma.sync.aligned.m16n8k16.row.col.f32.bf16.bf16.f32 "
                            "{%0,%1,%2,%3}, {%4,%5,%6,%7}, {%8,%9}, {%0,%1,%2,%3};"
                            : "+f"(acc[mt][nt][0]), "+f"(acc[mt][nt][1]),
                              "+f"(acc[mt][nt][2]), "+f"(acc[mt][nt][3])
                            : "r"(af[mt][0]), "r"(af[mt][1]), "r"(af[mt][2]), "r"(af[mt][3]),
                              "r"(b0), "r"(b1));
                    }
                }
            }
        }
        __syncthreads();
    }
#pragma unroll
    for (int mt = 0; mt < 2; mt++) {
        int r0 = m0 + warp_m + mt * 16 + (lane >> 2);
        int r1 = r0 + 8;
#pragma unroll
        for (int nt = 0; nt < NT; nt++) {
            int n0 = warp_n + nt * 8 + 2 * (lane & 3);
            if (r0 < N_NODES)
                __stcs((float2*)&Ch[(size_t)r0 * 128 + n0],
                       make_float2(acc[mt][nt][0], acc[mt][nt][1]));
            if (r1 < N_NODES)
                __stcs((float2*)&Ch[(size_t)r1 * 128 + n0],
                       make_float2(acc[mt][nt][2], acc[mt][nt][3]));
        }
    }
}

// layer2: single GEMM over M=200000 (shared W3), A pre-split bf16
__global__ void __launch_bounds__(256) gemm2_both() {
    constexpr int NT = 4;
    __shared__ __nv_bfloat16 sAh[128][SKP];
    __shared__ __nv_bfloat16 sAl[128][SKP];
    __shared__ __nv_bfloat16 sBh[64][SKP];
    __shared__ __nv_bfloat16 sBl[64][SKP];

    const int tid = threadIdx.x;
    const int wid = tid >> 5, lane = tid & 31;
    const int warp_m = (wid & 3) * 32;
    const int warp_n = (wid >> 2) * 32;
    const int m0 = blockIdx.x * 128;

    float acc[2][NT][4];
#pragma unroll
    for (int mt = 0; mt < 2; mt++)
#pragma unroll
        for (int nt = 0; nt < NT; nt++)
#pragma unroll
            for (int r = 0; r < 4; r++) acc[mt][nt][r] = 0.0f;

    const uint32_t sAh_b = smem_u32(&sAh[0][0]);
    const uint32_t sAl_b = smem_u32(&sAl[0][0]);
    const uint32_t sBh_b = smem_u32(&sBh[0][0]);
    const uint32_t sBl_b = smem_u32(&sBl[0][0]);
    const int a_row = warp_m + (lane & 15);
    const int a_khalf = (lane >> 4) << 3;
    const int b_row = warp_n + (lane & 7);
    const int b_khalf = lane & 8;

    for (int k0 = 0; k0 < 128; k0 += 32) {
#pragma unroll
        for (int it = 0; it < 2; it++) {
            int i = tid + it * 256;
            int r = i >> 2, q = i & 3;
            uint4 vh = make_uint4(0, 0, 0, 0), vl = make_uint4(0, 0, 0, 0);
            if (m0 + r < N2) {
                vh = *(const uint4*)&g_abh[(size_t)(m0 + r) * 128 + k0 + q * 8];
                vl = *(const uint4*)&g_abl[(size_t)(m0 + r) * 128 + k0 + q * 8];
            }
            *(uint4*)&sAh[r][q * 8] = vh;
            *(uint4*)&sAl[r][q * 8] = vl;
        }
        {
            int i = tid;
            int r = i >> 2, q = i & 3;
            *(uint4*)&sBh[r][q * 8] = *(const uint4*)&g_w3h[r * 128 + k0 + q * 8];
            *(uint4*)&sBl[r][q * 8] = *(const uint4*)&g_w3l[r * 128 + k0 + q * 8];
        }
        __syncthreads();
#pragma unroll
        for (int pass = 0; pass < 3; pass++) {
            const uint32_t aBase = (pass < 2) ? sAh_b : sAl_b;
            const uint32_t bBase = (pass == 1) ? sBl_b : sBh_b;
#pragma unroll
            for (int ks = 0; ks < 2; ks++) {
                uint32_t af[2][4];
#pragma unroll
                for (int mt = 0; mt < 2; mt++) {
                    uint32_t addr = aBase + ((a_row + mt * 16) * SKP + ks * 16 + a_khalf) * 2;
                    asm volatile("ldmatrix.sync.aligned.m8n8.x4.shared.b16 {%0,%1,%2,%3}, [%4];"
                        : "=r"(af[mt][0]), "=r"(af[mt][1]), "=r"(af[mt][2]), "=r"(af[mt][3])
                        : "r"(addr));
                }
#pragma unroll
                for (int nt = 0; nt < NT; nt++) {
                    uint32_t b0, b1;
                    uint32_t addr = bBase + ((b_row + nt * 8) * SKP + ks * 16 + b_khalf) * 2;
                    asm volatile("ldmatrix.sync.aligned.m8n8.x2.shared.b16 {%0,%1}, [%2];"
                        : "=r"(b0), "=r"(b1) : "r"(addr));
#pragma unroll
                    for (int mt = 0; mt < 2; mt++) {
                        asm volatile(
                            "mma.sync.aligned.m16n8k16.row.col.f32.bf16.bf16.f32 "
                            "{%0,%1,%2,%3}, {%4,%5,%6,%7}, {%8,%9}, {%0,%1,%2,%3};"
                            : "+f"(acc[mt][nt][0]), "+f"(acc[mt][nt][1]),
                              "+f"(acc[mt][nt][2]), "+f"(acc[mt][nt][3])
                            : "r"(af[mt][0]), "r"(af[mt][1]), "r"(af[mt][2]), "r"(af[mt][3]),
                              "r"(b0), "r"(b1));
                    }
                }
            }
        }
        __syncthreads();
    }
#pragma unroll
    for (int mt = 0; mt < 2; mt++) {
        int r0 = m0 + warp_m + mt * 16 + (lane >> 2);
        int r1 = r0 + 8;
#pragma unroll
        for (int nt = 0; nt < NT; nt++) {
            int n0 = warp_n + nt * 8 + 2 * (lane & 3);
            if (r0 < N2)
                __stcs((float2*)&g_h3[(size_t)r0 * 64 + n0],
                       make_float2(acc[mt][nt][0], acc[mt][nt][1]));
            if (r1 < N2)
                __stcs((float2*)&g_h3[(size_t)r1 * 64 + n0],
                       make_float2(acc[mt][nt][2], acc[mt][nt][3]));
        }
    }
}

// ---------------- CSR aggregation C=128, both nets; fused bias+relu+bf16 split ----------------
__global__ void __launch_bounds__(256) agg128_both(const float* __restrict__ b1,
                                                   const float* __restrict__ b2) {
    int node = blockIdx.x * 8 + (threadIdx.x >> 5);     // global row [0, 2N)
    int lane = threadIdx.x & 31;
    if (node >= N2) return;
    float inv = g_invdeg[node];
    float4 acc = *(const float4*)&g_h[(size_t)node * 128 + lane * 4];
    acc.x *= inv; acc.y *= inv; acc.z *= inv; acc.w *= inv;
    int i = g_rowstart[node], end = g_rowstart[node + 1];
    // 4-edge unrolled gather for MLP
    for (; i + 3 < end; i += 4) {
        int s0 = g_csr_src[i],     s1 = g_csr_src[i + 1];
        int s2 = g_csr_src[i + 2], s3 = g_csr_src[i + 3];
        float n0 = g_csr_norm[i],     n1 = g_csr_norm[i + 1];
        float n2 = g_csr_norm[i + 2], n3 = g_csr_norm[i + 3];
        float4 v0 = *(const float4*)&g_h[(size_t)s0 * 128 + lane * 4];
        float4 v1 = *(const float4*)&g_h[(size_t)s1 * 128 + lane * 4];
        float4 v2 = *(const float4*)&g_h[(size_t)s2 * 128 + lane * 4];
        float4 v3 = *(const float4*)&g_h[(size_t)s3 * 128 + lane * 4];
        acc.x = fmaf(v0.x, n0, fmaf(v1.x, n1, fmaf(v2.x, n2, fmaf(v3.x, n3, acc.x))));
        acc.y = fmaf(v0.y, n0, fmaf(v1.y, n1, fmaf(v2.y, n2, fmaf(v3.y, n3, acc.y))));
        acc.z = fmaf(v0.z, n0, fmaf(v1.z, n1, fmaf(v2.z, n2, fmaf(v3.z, n3, acc.z))));
        acc.w = fmaf(v0.w, n0, fmaf(v1.w, n1, fmaf(v2.w, n2, fmaf(v3.w, n3, acc.w))));
    }
    for (; i < end; i++) {
        int s0 = g_csr_src[i];
        float n0 = g_csr_norm[i];
        float4 v0 = *(const float4*)&g_h[(size_t)s0 * 128 + lane * 4];
        acc.x = fmaf(v0.x, n0, acc.x);
        acc.y = fmaf(v0.y, n0, acc.y);
        acc.z = fmaf(v0.z, n0, acc.z);
        acc.w = fmaf(v0.w, n0, acc.w);
    }
    const float* b = (node >= N_NODES) ? b2 : b1;
    float4 bb = ((const float4*)b)[lane];
    acc.x = fmaxf(acc.x + bb.x, 0.f); acc.y = fmaxf(acc.y + bb.y, 0.f);
    acc.z = fmaxf(acc.z + bb.z, 0.f); acc.w = fmaxf(acc.w + bb.w, 0.f);
    __nv_bfloat16 h0, h1, h2, h3, l0, l1, l2, l3;
    split_bf16(acc.x, h0, l0); split_bf16(acc.y, h1, l1);
    split_bf16(acc.z, h2, l2); split_bf16(acc.w, h3, l3);
    __nv_bfloat162 ph0 = {h0, h1}, ph1 = {h2, h3}, pl0 = {l0, l1}, pl1 = {l2, l3};
    size_t idx = (size_t)node * 32 + lane;
    ((uint2*)g_abh)[idx] = make_uint2(*(uint32_t*)&ph0, *(uint32_t*)&ph1);
    ((uint2*)g_abl)[idx] = make_uint2(*(uint32_t*)&pl0, *(uint32_t*)&pl1);
}

// ---------------- CSR aggregation C=64, both nets; fused +b3 -> zs|zt ----------------
__global__ void __launch_bounds__(256) agg64_both(const float* __restrict__ b3,
                                                  float* __restrict__ out) {
    int node = blockIdx.x * 16 + (threadIdx.x >> 4);
    int l = threadIdx.x & 15;
    if (node >= N2) return;
    float inv = g_invdeg[node];
    float4 acc = *(const float4*)&g_h3[(size_t)node * 64 + l * 4];
    acc.x *= inv; acc.y *= inv; acc.z *= inv; acc.w *= inv;
    int i = g_rowstart[node], end = g_rowstart[node + 1];
    for (; i + 3 < end; i += 4) {
        int s0 = g_csr_src[i],     s1 = g_csr_src[i + 1];
        int s2 = g_csr_src[i + 2], s3 = g_csr_src[i + 3];
        float n0 = g_csr_norm[i],     n1 = g_csr_norm[i + 1];
        float n2 = g_csr_norm[i + 2], n3 = g_csr_norm[i + 3];
        float4 v0 = *(const float4*)&g_h3[(size_t)s0 * 64 + l * 4];
        float4 v1 = *(const float4*)&g_h3[(size_t)s1 * 64 + l * 4];
        float4 v2 = *(const float4*)&g_h3[(size_t)s2 * 64 + l * 4];
        float4 v3 = *(const float4*)&g_h3[(size_t)s3 * 64 + l * 4];
        acc.x = fmaf(v0.x, n0, fmaf(v1.x, n1, fmaf(v2.x, n2, fmaf(v3.x, n3, acc.x))));
        acc.y = fmaf(v0.y, n0, fmaf(v1.y, n1, fmaf(v2.y, n2, fmaf(v3.y, n3, acc.y))));
        acc.z = fmaf(v0.z, n0, fmaf(v1.z, n1, fmaf(v2.z, n2, fmaf(v3.z, n3, acc.z))));
        acc.w = fmaf(v0.w, n0, fmaf(v1.w, n1, fmaf(v2.w, n2, fmaf(v3.w, n3, acc.w))));
    }
    for (; i < end; i++) {
        int s0 = g_csr_src[i];
        float n0 = g_csr_norm[i];
        float4 v0 = *(const float4*)&g_h3[(size_t)s0 * 64 + l * 4];
        acc.x = fmaf(v0.x, n0, acc.x);
        acc.y = fmaf(v0.y, n0, acc.y);
        acc.z = fmaf(v0.z, n0, acc.z);
        acc.w = fmaf(v0.w, n0, acc.w);
    }
    float4 bb = ((const float4*)b3)[l];
    acc.x += bb.x; acc.y += bb.y; acc.z += bb.z; acc.w += bb.w;
    *(float4*)&out[(size_t)node * 64 + l * 4] = acc;   // zs|zt contiguous
}

// ---------------- decoder, both nets ----------------
__global__ void decoder_both(const float* __restrict__ z, const int* __restrict__ s_ei,
                             const int* __restrict__ t_ei, float* __restrict__ p) {
    int gtid = blockIdx.x * blockDim.x + threadIdx.x;
    int eg = gtid >> 4;                 // [0, 2E)
    int l = gtid & 15;
    if (eg >= E2) return;
    int net = (eg >= N_EDGES);
    int e = eg - net * N_EDGES;
    const int* ei = net ? t_ei : s_ei;
    int base = net * N_NODES;
    int s = base + ei[e];
    int d = base + ei[N_EDGES + e];
    float4 a = *(const float4*)&z[(size_t)s * 64 + l * 4];
    float4 b = *(const float4*)&z[(size_t)d * 64 + l * 4];
    float v = a.x * b.x + a.y * b.y + a.z * b.z + a.w * b.w;
    v += __shfl_xor_sync(0xffffffffu, v, 8);
    v += __shfl_xor_sync(0xffffffffu, v, 4);
    v += __shfl_xor_sync(0xffffffffu, v, 2);
    v += __shfl_xor_sync(0xffffffffu, v, 1);
    if (l == 0) p[eg] = 1.0f / (1.0f + expf(-v));   // ps|pt contiguous
}

// ---------------- launch ----------------
extern "C" void kernel_launch(void* const* d_in, const int* in_sizes, int n_in,
                              void* d_out, int out_size) {
    const float* xs = (const float*)d_in[0];
    const float* xt = (const float*)d_in[1];
    const int* s_ei = (const int*)d_in[2];
    const int* t_ei = (const int*)d_in[3];
    const float* W1 = (const float*)d_in[4];
    const float* b1 = (const float*)d_in[5];
    const float* W2 = (const float*)d_in[6];
    const float* b2 = (const float*)d_in[7];
    const float* W3 = (const float*)d_in[8];
    const float* b3 = (const float*)d_in[9];

    float* out = (float*)d_out;
    float* z = out;                               // zs|zt [2N,64]
    float* p = out + (size_t)N2 * 64;             // ps|pt [2E]

    int* cnt;
    cudaGetSymbolAddress((void**)&cnt, g_cnt);

    const int NB_N2 = (N2 + 255) / 256;           // 782
    const int NB_E2 = (E2 + 255) / 256;           // 3907
    const int NB_G2 = (N2 + 127) / 128;           // 1563
    const int NB_A128 = (N2 + 7) / 8;             // 25000
    const int NB_A64 = (N2 + 15) / 16;            // 12500
    const int NB_DEC = (E2 * 16 + 255) / 256;     // 62500

    cudaStream_t s2 = g_side.s;

    // fork: CSR build chain on side stream, overlapped with prep+gemm1 on main
    cudaEventRecord(g_side.ev_fork, 0);
    cudaStreamWaitEvent(s2, g_side.ev_fork, 0);

    cudaMemsetAsync(cnt, 0, N2 * sizeof(int), s2);
    deg_count_both<<<NB_E2, 256, 0, s2>>>(s_ei, t_ei);
    scan1_kernel<<<NB_N2, 256, 0, s2>>>();
    scan2_kernel<<<1, 1024, 0, s2>>>(NB_N2);
    scan3_kernel<<<NB_N2, 256, 0, s2>>>();
    csr_fill_both<<<NB_E2, 256, 0, s2>>>(s_ei, t_ei);
    cudaEventRecord(g_side.ev_join, s2);

    prep_weights_kernel<<<64, 256>>>(W1, W2, W3);
    gemm1_both<<<2 * NB1, 256>>>(xs, xt);

    // join: agg128 needs both CSR and gemm1 output
    cudaStreamWaitEvent(0, g_side.ev_join, 0);

    agg128_both<<<NB_A128, 256>>>(b1, b2);
    gemm2_both<<<NB_G2, 256>>>();
    agg64_both<<<NB_A64, 256>>>(b3, z);
    decoder_both<<<NB_DEC, 256>>>(z, s_ei, t_ei, p);
}

// round 10
// speedup vs baseline: 1.8167x; 1.0351x over previous
#include <cuda_runtime.h>
#include <cuda_bf16.h>
#include <math.h>
#include <stdint.h>

#define N_NODES 100000
#define N_EDGES 500000
#define N2 (2 * N_NODES)      // 200000
#define E2 (2 * N_EDGES)      // 1000000
#define NB1 782               // gemm blocks per net (ceil(100000/128))

// ---------------- scratch (static device globals; no allocation) ----------------
__device__ float g_h[(size_t)N2 * 128];        // layer1 conv output, both nets
__device__ float g_h3[(size_t)N2 * 64];        // layer2 conv output, both nets
__device__ float g_dis[N2];
__device__ float g_invdeg[N2];
__device__ int g_cnt[N2];
__device__ int g_rowstart[N2 + 1];
__device__ int g_cursor[N2];
__device__ int g_blocksums[1024];
__device__ int g_csr_src[E2];                  // global rows (net*N + s)
__device__ int g_csr_eidx[E2];                 // original edge position (net*E + e)
__device__ float g_csr_norm[E2];
__device__ __nv_bfloat16 g_abh[(size_t)N2 * 128];
__device__ __nv_bfloat16 g_abl[(size_t)N2 * 128];
__device__ __nv_bfloat16 g_w1h[128 * 128], g_w1l[128 * 128];
__device__ __nv_bfloat16 g_w2h[128 * 128], g_w2l[128 * 128];
__device__ __nv_bfloat16 g_w3h[64 * 128],  g_w3l[64 * 128];

// ---------------- pre-created side stream + events (static init; NOT during capture) ----
struct SideStream {
    cudaStream_t s;
    cudaEvent_t ev_fork, ev_join;
    SideStream() {
        cudaStreamCreateWithFlags(&s, cudaStreamNonBlocking);
        cudaEventCreateWithFlags(&ev_fork, cudaEventDisableTiming);
        cudaEventCreateWithFlags(&ev_join, cudaEventDisableTiming);
    }
};
static SideStream g_side;

__device__ __forceinline__ uint32_t smem_u32(const void* p) {
    uint32_t a;
    asm("{ .reg .u64 t; cvta.to.shared.u64 t, %1; cvt.u32.u64 %0, t; }" : "=r"(a) : "l"(p));
    return a;
}
__device__ __forceinline__ void split_bf16(float v, __nv_bfloat16& hi, __nv_bfloat16& lo) {
    hi = __float2bfloat16_rn(v);
    lo = __float2bfloat16_rn(v - __bfloat162float(hi));
}

// ---------------- degree + CSR build (both nets concatenated) ----------------
__global__ void deg_count_both(const int* __restrict__ s_ei, const int* __restrict__ t_ei) {
    int g = blockIdx.x * blockDim.x + threadIdx.x;
    if (g >= E2) return;
    int net = (g >= N_EDGES);
    int e = g - net * N_EDGES;
    const int* ei = net ? t_ei : s_ei;
    int d = ei[N_EDGES + e];
    atomicAdd(&g_cnt[net * N_NODES + d], 1);
}

// block scan + deg finish fused
__global__ void scan1_kernel() {
    __shared__ int s[2][256];
    int tid = threadIdx.x;
    int i = blockIdx.x * 256 + tid;
    int v = (i < N2) ? g_cnt[i] : 0;
    if (i < N2) {
        float d = (float)v + 1.0f;
        g_dis[i] = rsqrtf(d);
        g_invdeg[i] = 1.0f / d;
    }
    int buf = 0;
    s[0][tid] = v;
    __syncthreads();
#pragma unroll
    for (int off = 1; off < 256; off <<= 1) {
        int nb = buf ^ 1;
        s[nb][tid] = s[buf][tid] + (tid >= off ? s[buf][tid - off] : 0);
        buf = nb;
        __syncthreads();
    }
    if (i < N2) g_rowstart[i] = s[buf][tid] - v;
    if (tid == 255) g_blocksums[blockIdx.x] = s[buf][255];
}
__global__ void scan2_kernel(int nblocks) {
    __shared__ int s[2][1024];
    int tid = threadIdx.x;
    int v = (tid < nblocks) ? g_blocksums[tid] : 0;
    int buf = 0;
    s[0][tid] = v;
    __syncthreads();
#pragma unroll
    for (int off = 1; off < 1024; off <<= 1) {
        int nb = buf ^ 1;
        s[nb][tid] = s[buf][tid] + (tid >= off ? s[buf][tid - off] : 0);
        buf = nb;
        __syncthreads();
    }
    g_blocksums[tid] = s[buf][tid] - v;
}
__global__ void scan3_kernel() {
    int i = blockIdx.x * blockDim.x + threadIdx.x;
    if (i < N2) {
        int rs = g_rowstart[i] + g_blocksums[i >> 8];
        g_rowstart[i] = rs;
        g_cursor[i] = rs;               // cursor starts at rowstart
    }
    if (i == 0) g_rowstart[N2] = E2;
}
__global__ void csr_fill_both(const int* __restrict__ s_ei, const int* __restrict__ t_ei) {
    int g = blockIdx.x * blockDim.x + threadIdx.x;
    if (g >= E2) return;
    int net = (g >= N_EDGES);
    int e = g - net * N_EDGES;
    const int* ei = net ? t_ei : s_ei;
    int s = net * N_NODES + ei[e];
    int d = net * N_NODES + ei[N_EDGES + e];
    int pos = atomicAdd(&g_cursor[d], 1);
    g_csr_src[pos] = s;
    g_csr_eidx[pos] = g;                // original (global) edge position
    g_csr_norm[pos] = g_dis[s] * g_dis[d];
}

// ---------------- weight prep ----------------
__global__ void prep_weights_kernel(const float* __restrict__ W1, const float* __restrict__ W2,
                                    const float* __restrict__ W3) {
    int tid = blockIdx.x * blockDim.x + threadIdx.x;
    if (tid < 128 * 128) {
        int n = tid >> 7, k = tid & 127;
        __nv_bfloat16 hi, lo;
        split_bf16(W1[k * 128 + n], hi, lo);
        g_w1h[n * 128 + k] = hi; g_w1l[n * 128 + k] = lo;
        split_bf16(W2[k * 128 + n], hi, lo);
        g_w2h[n * 128 + k] = hi; g_w2l[n * 128 + k] = lo;
        if (n < 64) {
            split_bf16(W3[k * 64 + n], hi, lo);
            g_w3h[n * 128 + k] = hi; g_w3l[n * 128 + k] = lo;
        }
    }
}

// ---------------- bf16-split HMMA GEMM core ----------------
#define SKP 40

// layer1: both nets in one launch (BN=128, A fp32 per-net)
__global__ void __launch_bounds__(256) gemm1_both(
        const float* __restrict__ xs, const float* __restrict__ xt) {
    constexpr int NT = 8;
    __shared__ __nv_bfloat16 sAh[128][SKP];
    __shared__ __nv_bfloat16 sAl[128][SKP];
    __shared__ __nv_bfloat16 sBh[128][SKP];
    __shared__ __nv_bfloat16 sBl[128][SKP];

    const int tid = threadIdx.x;
    const int wid = tid >> 5, lane = tid & 31;
    const int warp_m = (wid & 3) * 32;
    const int warp_n = (wid >> 2) * 64;
    const int net = (blockIdx.x >= NB1);
    const int m0 = (blockIdx.x - net * NB1) * 128;
    const float* Af = net ? xt : xs;
    const __nv_bfloat16* Bh_g = net ? g_w2h : g_w1h;
    const __nv_bfloat16* Bl_g = net ? g_w2l : g_w1l;
    float* Ch = g_h + (size_t)net * N_NODES * 128;

    float acc[2][NT][4];
#pragma unroll
    for (int mt = 0; mt < 2; mt++)
#pragma unroll
        for (int nt = 0; nt < NT; nt++)
#pragma unroll
            for (int r = 0; r < 4; r++) acc[mt][nt][r] = 0.0f;

    const uint32_t sAh_b = smem_u32(&sAh[0][0]);
    const uint32_t sAl_b = smem_u32(&sAl[0][0]);
    const uint32_t sBh_b = smem_u32(&sBh[0][0]);
    const uint32_t sBl_b = smem_u32(&sBl[0][0]);
    const int a_row = warp_m + (lane & 15);
    const int a_khalf = (lane >> 4) << 3;
    const int b_row = warp_n + (lane & 7);
    const int b_khalf = lane & 8;

    for (int k0 = 0; k0 < 128; k0 += 32) {
#pragma unroll
        for (int it = 0; it < 4; it++) {
            int i = tid + it * 256;
            int r = i >> 3, c = (i & 7) * 4;
            float4 v = make_float4(0.f, 0.f, 0.f, 0.f);
            if (m0 + r < N_NODES) v = *(const float4*)&Af[(size_t)(m0 + r) * 128 + k0 + c];
            __nv_bfloat16 h0, h1, h2, h3, l0, l1, l2, l3;
            split_bf16(v.x, h0, l0); split_bf16(v.y, h1, l1);
            split_bf16(v.z, h2, l2); split_bf16(v.w, h3, l3);
            __nv_bfloat162 ph0 = {h0, h1}, ph1 = {h2, h3};
            __nv_bfloat162 pl0 = {l0, l1}, pl1 = {l2, l3};
            *(uint2*)&sAh[r][c] = make_uint2(*(uint32_t*)&ph0, *(uint32_t*)&ph1);
            *(uint2*)&sAl[r][c] = make_uint2(*(uint32_t*)&pl0, *(uint32_t*)&pl1);
        }
#pragma unroll
        for (int it = 0; it < 2; it++) {
            int i = tid + it * 256;
            int r = i >> 2, q = i & 3;
            *(uint4*)&sBh[r][q * 8] = *(const uint4*)&Bh_g[r * 128 + k0 + q * 8];
            *(uint4*)&sBl[r][q * 8] = *(const uint4*)&Bl_g[r * 128 + k0 + q * 8];
        }
        __syncthreads();
#pragma unroll
        for (int pass = 0; pass < 3; pass++) {
            const uint32_t aBase = (pass < 2) ? sAh_b : sAl_b;
            const uint32_t bBase = (pass == 1) ? sBl_b : sBh_b;
#pragma unroll
            for (int ks = 0; ks < 2; ks++) {
                uint32_t af[2][4];
#pragma unroll
                for (int mt = 0; mt < 2; mt++) {
                    uint32_t addr = aBase + ((a_row + mt * 16) * SKP + ks * 16 + a_khalf) * 2;
                    asm volatile("ldmatrix.sync.aligned.m8n8.x4.shared.b16 {%0,%1,%2,%3}, [%4];"
                        : "=r"(af[mt][0]), "=r"(af[mt][1]), "=r"(af[mt][2]), "=r"(af[mt][3])
                        : "r"(addr));
                }
#pragma unroll
                for (int nt = 0; nt < NT; nt++) {
                    uint32_t b0, b1;
                    uint32_t addr = bBase + ((b_row + nt * 8) * SKP + ks * 16 + b_khalf) * 2;
                    asm volatile("ldmatrix.sync.aligned.m8n8.x2.shared.b16 {%0,%1}, [%2];"
                        : "=r"(b0), "=r"(b1) : "r"(addr));
#pragma unroll
                    for (int mt = 0; mt < 2; mt++) {
                        asm volatile(
                            "mma.sync.aligned.m16n8k16.row.col.f32.bf16.bf16.f32 "
                            "{%0,%1,%2,%3}, {%4,%5,%6,%7}, {%8,%9}, {%0,%1,%2,%3};"
                            : "+f"(acc[mt][nt][0]), "+f"(acc[mt][nt][1]),
                              "+f"(acc[mt][nt][2]), "+f"(acc[mt][nt][3])
                            : "r"(af[mt][0]), "r"(af[mt][1]), "r"(af[mt][2]), "r"(af[mt][3]),
                              "r"(b0), "r"(b1));
                    }
                }
            }
        }
        __syncthreads();
    }
#pragma unroll
    for (int mt = 0; mt < 2; mt++) {
        int r0 = m0 + warp_m + mt * 16 + (lane >> 2);
        int r1 = r0 + 8;
#pragma unroll
        for (int nt = 0; nt < NT; nt++) {
            int n0 = warp_n + nt * 8 + 2 * (lane & 3);
            if (r0 < N_NODES)
                __stcs((float2*)&Ch[(size_t)r0 * 128 + n0],
                       make_float2(acc[mt][nt][0], acc[mt][nt][1]));
            if (r1 < N_NODES)
                __stcs((float2*)&Ch[(size_t)r1 * 128 + n0],
                       make_float2(acc[mt][nt][2], acc[mt][nt][3]));
        }
    }
}

// layer2: single GEMM over M=200000 (shared W3), A pre-split bf16
__global__ void __launch_bounds__(256) gemm2_both() {
    constexpr int NT = 4;
    __shared__ __nv_bfloat16 sAh[128][SKP];
    __shared__ __nv_bfloat16 sAl[128][SKP];
    __shared__ __nv_bfloat16 sBh[64][SKP];
    __shared__ __nv_bfloat16 sBl[64][SKP];

    const int tid = threadIdx.x;
    const int wid = tid >> 5, lane = tid & 31;
    const int warp_m = (wid & 3) * 32;
    const int warp_n = (wid >> 2) * 32;
    const int m0 = blockIdx.x * 128;

    float acc[2][NT][4];
#pragma unroll
    for (int mt = 0; mt < 2; mt++)
#pragma unroll
        for (int nt = 0; nt < NT; nt++)
#pragma unroll
            for (int r = 0; r < 4; r++) acc[mt][nt][r] = 0.0f;

    const uint32_t sAh_b = smem_u32(&sAh[0][0]);
    const uint32_t sAl_b = smem_u32(&sAl[0][0]);
    const uint32_t sBh_b = smem_u32(&sBh[0][0]);
    const uint32_t sBl_b = smem_u32(&sBl[0][0]);
    const int a_row = warp_m + (lane & 15);
    const int a_khalf = (lane >> 4) << 3;
    const int b_row = warp_n + (lane & 7);
    const int b_khalf = lane & 8;

    for (int k0 = 0; k0 < 128; k0 += 32) {
#pragma unroll
        for (int it = 0; it < 2; it++) {
            int i = tid + it * 256;
            int r = i >> 2, q = i & 3;
            uint4 vh = make_uint4(0, 0, 0, 0), vl = make_uint4(0, 0, 0, 0);
            if (m0 + r < N2) {
                vh = *(const uint4*)&g_abh[(size_t)(m0 + r) * 128 + k0 + q * 8];
                vl = *(const uint4*)&g_abl[(size_t)(m0 + r) * 128 + k0 + q * 8];
            }
            *(uint4*)&sAh[r][q * 8] = vh;
            *(uint4*)&sAl[r][q * 8] = vl;
        }
        {
            int i = tid;
            int r = i >> 2, q = i & 3;
            *(uint4*)&sBh[r][q * 8] = *(const uint4*)&g_w3h[r * 128 + k0 + q * 8];
            *(uint4*)&sBl[r][q * 8] = *(const uint4*)&g_w3l[r * 128 + k0 + q * 8];
        }
        __syncthreads();
#pragma unroll
        for (int pass = 0; pass < 3; pass++) {
            const uint32_t aBase = (pass < 2) ? sAh_b : sAl_b;
            const uint32_t bBase = (pass == 1) ? sBl_b : sBh_b;
#pragma unroll
            for (int ks = 0; ks < 2; ks++) {
                uint32_t af[2][4];
#pragma unroll
                for (int mt = 0; mt < 2; mt++) {
                    uint32_t addr = aBase + ((a_row + mt * 16) * SKP + ks * 16 + a_khalf) * 2;
                    asm volatile("ldmatrix.sync.aligned.m8n8.x4.shared.b16 {%0,%1,%2,%3}, [%4];"
                        : "=r"(af[mt][0]), "=r"(af[mt][1]), "=r"(af[mt][2]), "=r"(af[mt][3])
                        : "r"(addr));
                }
#pragma unroll
                for (int nt = 0; nt < NT; nt++) {
                    uint32_t b0, b1;
                    uint32_t addr = bBase + ((b_row + nt * 8) * SKP + ks * 16 + b_khalf) * 2;
                    asm volatile("ldmatrix.sync.aligned.m8n8.x2.shared.b16 {%0,%1}, [%2];"
                        : "=r"(b0), "=r"(b1) : "r"(addr));
#pragma unroll
                    for (int mt = 0; mt < 2; mt++) {
                        asm volatile(
                            "mma.sync.aligned.m16n8k16.row.col.f32.bf16.bf16.f32 "
                            "{%0,%1,%2,%3}, {%4,%5,%6,%7}, {%8,%9}, {%0,%1,%2,%3};"
                            : "+f"(acc[mt][nt][0]), "+f"(acc[mt][nt][1]),
                              "+f"(acc[mt][nt][2]), "+f"(acc[mt][nt][3])
                            : "r"(af[mt][0]), "r"(af[mt][1]), "r"(af[mt][2]), "r"(af[mt][3]),
                              "r"(b0), "r"(b1));
                    }
                }
            }
        }
        __syncthreads();
    }
#pragma unroll
    for (int mt = 0; mt < 2; mt++) {
        int r0 = m0 + warp_m + mt * 16 + (lane >> 2);
        int r1 = r0 + 8;
#pragma unroll
        for (int nt = 0; nt < NT; nt++) {
            int n0 = warp_n + nt * 8 + 2 * (lane & 3);
            if (r0 < N2)
                __stcs((float2*)&g_h3[(size_t)r0 * 64 + n0],
                       make_float2(acc[mt][nt][0], acc[mt][nt][1]));
            if (r1 < N2)
                __stcs((float2*)&g_h3[(size_t)r1 * 64 + n0],
                       make_float2(acc[mt][nt][2], acc[mt][nt][3]));
        }
    }
}

// ---------------- CSR aggregation C=128, both nets; fused bias+relu+bf16 split ----------------
__global__ void __launch_bounds__(256) agg128_both(const float* __restrict__ b1,
                                                   const float* __restrict__ b2) {
    int node = blockIdx.x * 8 + (threadIdx.x >> 5);     // global row [0, 2N)
    int lane = threadIdx.x & 31;
    if (node >= N2) return;
    float inv = g_invdeg[node];
    float4 acc = *(const float4*)&g_h[(size_t)node * 128 + lane * 4];
    acc.x *= inv; acc.y *= inv; acc.z *= inv; acc.w *= inv;
    int i = g_rowstart[node], end = g_rowstart[node + 1];
    // 4-edge unrolled gather for MLP
    for (; i + 3 < end; i += 4) {
        int s0 = g_csr_src[i],     s1 = g_csr_src[i + 1];
        int s2 = g_csr_src[i + 2], s3 = g_csr_src[i + 3];
        float n0 = g_csr_norm[i],     n1 = g_csr_norm[i + 1];
        float n2 = g_csr_norm[i + 2], n3 = g_csr_norm[i + 3];
        float4 v0 = *(const float4*)&g_h[(size_t)s0 * 128 + lane * 4];
        float4 v1 = *(const float4*)&g_h[(size_t)s1 * 128 + lane * 4];
        float4 v2 = *(const float4*)&g_h[(size_t)s2 * 128 + lane * 4];
        float4 v3 = *(const float4*)&g_h[(size_t)s3 * 128 + lane * 4];
        acc.x = fmaf(v0.x, n0, fmaf(v1.x, n1, fmaf(v2.x, n2, fmaf(v3.x, n3, acc.x))));
        acc.y = fmaf(v0.y, n0, fmaf(v1.y, n1, fmaf(v2.y, n2, fmaf(v3.y, n3, acc.y))));
        acc.z = fmaf(v0.z, n0, fmaf(v1.z, n1, fmaf(v2.z, n2, fmaf(v3.z, n3, acc.z))));
        acc.w = fmaf(v0.w, n0, fmaf(v1.w, n1, fmaf(v2.w, n2, fmaf(v3.w, n3, acc.w))));
    }
    for (; i < end; i++) {
        int s0 = g_csr_src[i];
        float n0 = g_csr_norm[i];
        float4 v0 = *(const float4*)&g_h[(size_t)s0 * 128 + lane * 4];
        acc.x = fmaf(v0.x, n0, acc.x);
        acc.y = fmaf(v0.y, n0, acc.y);
        acc.z = fmaf(v0.z, n0, acc.z);
        acc.w = fmaf(v0.w, n0, acc.w);
    }
    const float* b = (node >= N_NODES) ? b2 : b1;
    float4 bb = ((const float4*)b)[lane];
    acc.x = fmaxf(acc.x + bb.x, 0.f); acc.y = fmaxf(acc.y + bb.y, 0.f);
    acc.z = fmaxf(acc.z + bb.z, 0.f); acc.w = fmaxf(acc.w + bb.w, 0.f);
    __nv_bfloat16 h0, h1, h2, h3, l0, l1, l2, l3;
    split_bf16(acc.x, h0, l0); split_bf16(acc.y, h1, l1);
    split_bf16(acc.z, h2, l2); split_bf16(acc.w, h3, l3);
    __nv_bfloat162 ph0 = {h0, h1}, ph1 = {h2, h3}, pl0 = {l0, l1}, pl1 = {l2, l3};
    size_t idx = (size_t)node * 32 + lane;
    // streaming stores: keep h resident in L2 for the gathers
    __stcs((uint2*)&((uint2*)g_abh)[idx], make_uint2(*(uint32_t*)&ph0, *(uint32_t*)&ph1));
    __stcs((uint2*)&((uint2*)g_abl)[idx], make_uint2(*(uint32_t*)&pl0, *(uint32_t*)&pl1));
}

// ---------------- CSR aggregation C=64, both nets; fused +b3 -> zs|zt ----------------
__global__ void __launch_bounds__(256) agg64_both(const float* __restrict__ b3,
                                                  float* __restrict__ out) {
    int node = blockIdx.x * 16 + (threadIdx.x >> 4);
    int l = threadIdx.x & 15;
    if (node >= N2) return;
    float inv = g_invdeg[node];
    float4 acc = *(const float4*)&g_h3[(size_t)node * 64 + l * 4];
    acc.x *= inv; acc.y *= inv; acc.z *= inv; acc.w *= inv;
    int i = g_rowstart[node], end = g_rowstart[node + 1];
    for (; i + 3 < end; i += 4) {
        int s0 = g_csr_src[i],     s1 = g_csr_src[i + 1];
        int s2 = g_csr_src[i + 2], s3 = g_csr_src[i + 3];
        float n0 = g_csr_norm[i],     n1 = g_csr_norm[i + 1];
        float n2 = g_csr_norm[i + 2], n3 = g_csr_norm[i + 3];
        float4 v0 = *(const float4*)&g_h3[(size_t)s0 * 64 + l * 4];
        float4 v1 = *(const float4*)&g_h3[(size_t)s1 * 64 + l * 4];
        float4 v2 = *(const float4*)&g_h3[(size_t)s2 * 64 + l * 4];
        float4 v3 = *(const float4*)&g_h3[(size_t)s3 * 64 + l * 4];
        acc.x = fmaf(v0.x, n0, fmaf(v1.x, n1, fmaf(v2.x, n2, fmaf(v3.x, n3, acc.x))));
        acc.y = fmaf(v0.y, n0, fmaf(v1.y, n1, fmaf(v2.y, n2, fmaf(v3.y, n3, acc.y))));
        acc.z = fmaf(v0.z, n0, fmaf(v1.z, n1, fmaf(v2.z, n2, fmaf(v3.z, n3, acc.z))));
        acc.w = fmaf(v0.w, n0, fmaf(v1.w, n1, fmaf(v2.w, n2, fmaf(v3.w, n3, acc.w))));
    }
    for (; i < end; i++) {
        int s0 = g_csr_src[i];
        float n0 = g_csr_norm[i];
        float4 v0 = *(const float4*)&g_h3[(size_t)s0 * 64 + l * 4];
        acc.x = fmaf(v0.x, n0, acc.x);
        acc.y = fmaf(v0.y, n0, acc.y);
        acc.z = fmaf(v0.z, n0, acc.z);
        acc.w = fmaf(v0.w, n0, acc.w);
    }
    float4 bb = ((const float4*)b3)[l];
    acc.x += bb.x; acc.y += bb.y; acc.z += bb.z; acc.w += bb.w;
    *(float4*)&out[(size_t)node * 64 + l * 4] = acc;   // zs|zt contiguous
}

// ---------------- decoder, CSR-ordered: z[dst] loaded once per node ----------------
// half-warp (16 lanes) per dst node; lane owns 4 of 64 cols
__global__ void __launch_bounds__(256) decoder_csr(const float* __restrict__ z,
                                                   float* __restrict__ p) {
    int node = blockIdx.x * 16 + (threadIdx.x >> 4);
    int l = threadIdx.x & 15;
    if (node >= N2) return;
    float4 zd = *(const float4*)&z[(size_t)node * 64 + l * 4];
    int i = g_rowstart[node], end = g_rowstart[node + 1];
    for (; i + 1 < end; i += 2) {
        int s0 = g_csr_src[i], s1 = g_csr_src[i + 1];
        int e0 = g_csr_eidx[i], e1 = g_csr_eidx[i + 1];
        float4 a0 = *(const float4*)&z[(size_t)s0 * 64 + l * 4];
        float4 a1 = *(const float4*)&z[(size_t)s1 * 64 + l * 4];
        float v0 = a0.x * zd.x + a0.y * zd.y + a0.z * zd.z + a0.w * zd.w;
        float v1 = a1.x * zd.x + a1.y * zd.y + a1.z * zd.z + a1.w * zd.w;
        v0 += __shfl_xor_sync(0xffffffffu, v0, 8);
        v1 += __shfl_xor_sync(0xffffffffu, v1, 8);
        v0 += __shfl_xor_sync(0xffffffffu, v0, 4);
        v1 += __shfl_xor_sync(0xffffffffu, v1, 4);
        v0 += __shfl_xor_sync(0xffffffffu, v0, 2);
        v1 += __shfl_xor_sync(0xffffffffu, v1, 2);
        v0 += __shfl_xor_sync(0xffffffffu, v0, 1);
        v1 += __shfl_xor_sync(0xffffffffu, v1, 1);
        if (l == 0) {
            p[e0] = 1.0f / (1.0f + expf(-v0));
            p[e1] = 1.0f / (1.0f + expf(-v1));
        }
    }
    if (i < end) {
        int s0 = g_csr_src[i];
        int e0 = g_csr_eidx[i];
        float4 a0 = *(const float4*)&z[(size_t)s0 * 64 + l * 4];
        float v0 = a0.x * zd.x + a0.y * zd.y + a0.z * zd.z + a0.w * zd.w;
        v0 += __shfl_xor_sync(0xffffffffu, v0, 8);
        v0 += __shfl_xor_sync(0xffffffffu, v0, 4);
        v0 += __shfl_xor_sync(0xffffffffu, v0, 2);
        v0 += __shfl_xor_sync(0xffffffffu, v0, 1);
        if (l == 0) p[e0] = 1.0f / (1.0f + expf(-v0));
    }
}

// ---------------- launch ----------------
extern "C" void kernel_launch(void* const* d_in, const int* in_sizes, int n_in,
                              void* d_out, int out_size) {
    const float* xs = (const float*)d_in[0];
    const float* xt = (const float*)d_in[1];
    const int* s_ei = (const int*)d_in[2];
    const int* t_ei = (const int*)d_in[3];
    const float* W1 = (const float*)d_in[4];
    const float* b1 = (const float*)d_in[5];
    const float* W2 = (const float*)d_in[6];
    const float* b2 = (const float*)d_in[7];
    const float* W3 = (const float*)d_in[8];
    const float* b3 = (const float*)d_in[9];

    float* out = (float*)d_out;
    float* z = out;                               // zs|zt [2N,64]
    float* p = out + (size_t)N2 * 64;             // ps|pt [2E]

    int* cnt;
    cudaGetSymbolAddress((void**)&cnt, g_cnt);

    const int NB_N2 = (N2 + 255) / 256;           // 782
    const int NB_E2 = (E2 + 255) / 256;           // 3907
    const int NB_G2 = (N2 + 127) / 128;           // 1563
    const int NB_A128 = (N2 + 7) / 8;             // 25000
    const int NB_A64 = (N2 + 15) / 16;            // 12500

    cudaStream_t s2 = g_side.s;

    // fork: CSR build chain on side stream, overlapped with prep+gemm1 on main
    cudaEventRecord(g_side.ev_fork, 0);
    cudaStreamWaitEvent(s2, g_side.ev_fork, 0);

    cudaMemsetAsync(cnt, 0, N2 * sizeof(int), s2);
    deg_count_both<<<NB_E2, 256, 0, s2>>>(s_ei, t_ei);
    scan1_kernel<<<NB_N2, 256, 0, s2>>>();
    scan2_kernel<<<1, 1024, 0, s2>>>(NB_N2);
    scan3_kernel<<<NB_N2, 256, 0, s2>>>();
    csr_fill_both<<<NB_E2, 256, 0, s2>>>(s_ei, t_ei);
    cudaEventRecord(g_side.ev_join, s2);

    prep_weights_kernel<<<64, 256>>>(W1, W2, W3);
    gemm1_both<<<2 * NB1, 256>>>(xs, xt);

    // join: agg128 needs both CSR and gemm1 output
    cudaStreamWaitEvent(0, g_side.ev_join, 0);

    agg128_both<<<NB_A128, 256>>>(b1, b2);
    gemm2_both<<<NB_G2, 256>>>();
    agg64_both<<<NB_A64, 256>>>(b3, z);
    decoder_csr<<<NB_A64, 256>>>(z, p);
}